// round 1
// baseline (speedup 1.0000x reference)
#include <cuda_runtime.h>

#define NSVC 50000
#define NNODE 20000
#define NPOD 100000
#define FD 128
#define OUTD 64

// ---- degree array layout (int counters) ----
#define DEG_SVC_SRC 0
#define DEG_SVC_DST (NSVC)
#define DEG_PN_SRC  (2*NSVC)
#define DEG_PN_DST  (2*NSVC + NPOD)
#define DEG_NP_SRC  (2*NSVC + NPOD + NNODE)
#define DEG_NP_DST  (2*NSVC + NPOD + 2*NNODE)
#define DEG_TOTAL   (2*NSVC + 2*NPOD + 2*NNODE)

// ---- aggregation scratch layout (float) ----
#define AGG_SVC_OFF  ((size_t)0)
#define AGG_NODE_OFF ((size_t)NSVC * FD)
#define AGG_POD_OFF  ((size_t)(NSVC + NNODE) * FD)
#define AGG_TOTAL    ((size_t)(NSVC + NNODE + NPOD) * FD)

__device__ float g_agg[AGG_TOTAL];
__device__ int   g_deg[DEG_TOTAL];

// ============================================================
// K1: zero scratch
// ============================================================
__global__ void zero_kernel() {
    size_t n4 = AGG_TOTAL / 4;
    float4 z = make_float4(0.f, 0.f, 0.f, 0.f);
    float4* p = reinterpret_cast<float4*>(g_agg);
    size_t stride = (size_t)gridDim.x * blockDim.x;
    for (size_t i = (size_t)blockIdx.x * blockDim.x + threadIdx.x; i < n4; i += stride)
        p[i] = z;
    for (size_t i = (size_t)blockIdx.x * blockDim.x + threadIdx.x; i < DEG_TOTAL; i += stride)
        g_deg[i] = 0;
}

// ============================================================
// K2: degree counting (src & dst) for one edge type
// ============================================================
__global__ void deg_kernel(const int* __restrict__ src, const int* __restrict__ dst,
                           int E, int off_s, int off_d) {
    int i = blockIdx.x * blockDim.x + threadIdx.x;
    if (i < E) {
        atomicAdd(&g_deg[off_s + src[i]], 1);
        atomicAdd(&g_deg[off_d + dst[i]], 1);
    }
}

// ============================================================
// K3: edge scatter. One warp per edge: lane l handles float4 l.
//     msg = x[src] * rsqrt(deg_src); agg[dst] += msg  (v4 reduction)
// ============================================================
__global__ void scatter_kernel(const float* __restrict__ x,
                               const int* __restrict__ src,
                               const int* __restrict__ dst,
                               int E, int deg_src_off, size_t agg_off) {
    int w = (blockIdx.x * blockDim.x + threadIdx.x) >> 5;
    int lane = threadIdx.x & 31;
    if (w >= E) return;
    int s = __ldg(src + w);
    int d = __ldg(dst + w);
    int ds = g_deg[deg_src_off + s];
    float ns = rsqrtf((float)(ds > 1 ? ds : 1));
    float4 v = reinterpret_cast<const float4*>(x)[(size_t)s * 32 + lane];
    v.x *= ns; v.y *= ns; v.z *= ns; v.w *= ns;
    float* a = g_agg + agg_off + (size_t)d * FD + lane * 4;
    asm volatile("red.global.add.v4.f32 [%0], {%1,%2,%3,%4};"
                 :: "l"(a), "f"(v.x), "f"(v.y), "f"(v.z), "f"(v.w) : "memory");
}

// ============================================================
// K4: fused per-type epilogue:
//     out = leaky( (agg * rsqrt(deg_dst)) @ W1 + b1 ) @ W2 + b2
// block = 128 threads, 128 rows/block. W1/W2/A-tile staged in smem.
// A-tile padded to 129 floats/row -> conflict-free per-lane reads.
// ============================================================
#define GEMM_SMEM_FLOATS (128*128 + 128*64 + 128*129 + 128 + 128 + 64)

__global__ void gemm_fused(size_t agg_off, int deg_off,
                           const float* __restrict__ W1, const float* __restrict__ b1,
                           const float* __restrict__ W2, const float* __restrict__ b2,
                           float* __restrict__ out, int M) {
    extern __shared__ float sm[];
    float* W1s = sm;                    // 128*128
    float* W2s = W1s + 128 * 128;       // 128*64
    float* As  = W2s + 128 * 64;        // 128*129 (padded)
    float* nrm = As + 128 * 129;        // 128
    float* b1s = nrm + 128;             // 128
    float* b2s = b1s + 128;             // 64

    int tid = threadIdx.x;  // 128 threads

    // stage weights
    {
        const float4* s4 = reinterpret_cast<const float4*>(W1);
        float4* d4 = reinterpret_cast<float4*>(W1s);
        #pragma unroll
        for (int i = 0; i < 32; i++) d4[i * 128 + tid] = s4[i * 128 + tid];
    }
    {
        const float4* s4 = reinterpret_cast<const float4*>(W2);
        float4* d4 = reinterpret_cast<float4*>(W2s);
        #pragma unroll
        for (int i = 0; i < 16; i++) d4[i * 128 + tid] = s4[i * 128 + tid];
    }
    b1s[tid] = b1[tid];
    if (tid < 64) b2s[tid] = b2[tid];

    int row0 = blockIdx.x * 128;
    int row  = row0 + tid;
    if (row < M) {
        int dd = g_deg[deg_off + row];
        nrm[tid] = rsqrtf((float)(dd > 1 ? dd : 1));
    } else {
        nrm[tid] = 0.f;
    }
    __syncthreads();

    // cooperative, coalesced A-tile load with dst-norm applied
    const float4* av = reinterpret_cast<const float4*>(g_agg + agg_off);
    #pragma unroll
    for (int it = 0; it < 32; it++) {
        int f4i = it * 128 + tid;
        int r = f4i >> 5, c = f4i & 31;
        float4 v = make_float4(0.f, 0.f, 0.f, 0.f);
        if (row0 + r < M) v = av[(size_t)(row0 + r) * 32 + c];
        float nn = nrm[r];
        float* dp = As + r * 129 + c * 4;
        dp[0] = v.x * nn; dp[1] = v.y * nn; dp[2] = v.z * nn; dp[3] = v.w * nn;
    }
    __syncthreads();

    if (row >= M) return;

    float o[64];
    #pragma unroll
    for (int n = 0; n < 64; n++) o[n] = b2s[n];

    const float* arow = As + tid * 129;

    #pragma unroll
    for (int c = 0; c < 4; c++) {            // hidden columns in chunks of 32
        float h[32];
        #pragma unroll
        for (int j = 0; j < 32; j++) h[j] = b1s[c * 32 + j];

        #pragma unroll 4
        for (int k = 0; k < 128; k++) {
            float a = arow[k];
            const float4* wr = reinterpret_cast<const float4*>(W1s + k * 128 + c * 32);
            #pragma unroll
            for (int j4 = 0; j4 < 8; j4++) {
                float4 w = wr[j4];
                h[j4 * 4 + 0] += a * w.x;
                h[j4 * 4 + 1] += a * w.y;
                h[j4 * 4 + 2] += a * w.z;
                h[j4 * 4 + 3] += a * w.w;
            }
        }
        // leaky + second GEMM accumulation
        #pragma unroll
        for (int j = 0; j < 32; j++) {
            float hv = h[j];
            float lh = hv > 0.f ? hv : 0.01f * hv;
            const float4* w2r = reinterpret_cast<const float4*>(W2s + (c * 32 + j) * 64);
            #pragma unroll
            for (int n4 = 0; n4 < 16; n4++) {
                float4 w = w2r[n4];
                o[n4 * 4 + 0] += lh * w.x;
                o[n4 * 4 + 1] += lh * w.y;
                o[n4 * 4 + 2] += lh * w.z;
                o[n4 * 4 + 3] += lh * w.w;
            }
        }
    }

    float4* ov = reinterpret_cast<float4*>(out) + (size_t)row * 16;
    #pragma unroll
    for (int n4 = 0; n4 < 16; n4++)
        ov[n4] = make_float4(o[n4 * 4], o[n4 * 4 + 1], o[n4 * 4 + 2], o[n4 * 4 + 3]);
}

// ============================================================
// launch
// ============================================================
extern "C" void kernel_launch(void* const* d_in, const int* in_sizes, int n_in,
                              void* d_out, int out_size) {
    const float* x_svc  = (const float*)d_in[0];
    const float* x_pod  = (const float*)d_in[1];
    const float* x_node = (const float*)d_in[2];
    const int* svc_src = (const int*)d_in[3];
    const int* svc_dst = (const int*)d_in[4];
    const int* pn_src  = (const int*)d_in[5];
    const int* pn_dst  = (const int*)d_in[6];
    const int* np_src  = (const int*)d_in[7];
    const int* np_dst  = (const int*)d_in[8];
    const float* W_call = (const float*)d_in[9];
    const float* b_call = (const float*)d_in[10];
    const float* W_in   = (const float*)d_in[11];
    const float* b_in   = (const float*)d_in[12];
    const float* W_ni   = (const float*)d_in[13];
    const float* b_ni   = (const float*)d_in[14];
    const float* W_lin_svc  = (const float*)d_in[15];
    const float* b_lin_svc  = (const float*)d_in[16];
    const float* W_lin_node = (const float*)d_in[17];
    const float* b_lin_node = (const float*)d_in[18];
    const float* W_lin_pod  = (const float*)d_in[19];
    const float* b_lin_pod  = (const float*)d_in[20];
    float* out = (float*)d_out;

    int E_svc = in_sizes[3];
    int E_pn  = in_sizes[5];
    int E_np  = in_sizes[7];

    size_t smem = GEMM_SMEM_FLOATS * sizeof(float);
    cudaFuncSetAttribute(gemm_fused, cudaFuncAttributeMaxDynamicSharedMemorySize, (int)smem);

    zero_kernel<<<2048, 256>>>();

    deg_kernel<<<(E_svc + 255) / 256, 256>>>(svc_src, svc_dst, E_svc, DEG_SVC_SRC, DEG_SVC_DST);
    deg_kernel<<<(E_pn  + 255) / 256, 256>>>(pn_src,  pn_dst,  E_pn,  DEG_PN_SRC,  DEG_PN_DST);
    deg_kernel<<<(E_np  + 255) / 256, 256>>>(np_src,  np_dst,  E_np,  DEG_NP_SRC,  DEG_NP_DST);

    // scatter: 1 warp/edge -> blocks = ceil(E/8) with 256 threads
    scatter_kernel<<<(E_svc + 7) / 8, 256>>>(x_svc,  svc_src, svc_dst, E_svc, DEG_SVC_SRC, AGG_SVC_OFF);
    scatter_kernel<<<(E_pn  + 7) / 8, 256>>>(x_pod,  pn_src,  pn_dst,  E_pn,  DEG_PN_SRC,  AGG_NODE_OFF);
    scatter_kernel<<<(E_np  + 7) / 8, 256>>>(x_node, np_src,  np_dst,  E_np,  DEG_NP_SRC,  AGG_POD_OFF);

    // fused norm + GEMM + leaky + GEMM per node type, writing concat slices
    gemm_fused<<<(NSVC  + 127) / 128, 128, smem>>>(AGG_SVC_OFF,  DEG_SVC_DST, W_call, b_call,
                                                   W_lin_svc,  b_lin_svc,  out,                              NSVC);
    gemm_fused<<<(NNODE + 127) / 128, 128, smem>>>(AGG_NODE_OFF, DEG_PN_DST,  W_in,   b_in,
                                                   W_lin_node, b_lin_node, out + (size_t)NSVC * OUTD,        NNODE);
    gemm_fused<<<(NPOD  + 127) / 128, 128, smem>>>(AGG_POD_OFF,  DEG_NP_DST,  W_ni,   b_ni,
                                                   W_lin_pod,  b_lin_pod,  out + (size_t)(NSVC+NNODE) * OUTD, NPOD);
}

// round 2
// speedup vs baseline: 1.6307x; 1.6307x over previous
#include <cuda_runtime.h>

#define NSVC 50000
#define NNODE 20000
#define NPOD 100000
#define FD 128
#define OUTD 64
#define ESVC_MAX 1600000
#define EPN_MAX  100000
#define ENP_MAX  100000

// ---- degree/norm array layout ----
#define DEG_SVC_SRC 0
#define DEG_SVC_DST (NSVC)
#define DEG_PN_SRC  (2*NSVC)
#define DEG_PN_DST  (2*NSVC + NPOD)
#define DEG_NP_SRC  (2*NSVC + NPOD + NNODE)
#define DEG_NP_DST  (2*NSVC + NPOD + 2*NNODE)
#define DEG_TOTAL   (2*NSVC + 2*NPOD + 2*NNODE)

// ---- per-type CSR offset arrays ----
#define OFF_SVC  0
#define OFF_NODE (NSVC)
#define OFF_POD  (NSVC + NNODE)
#define OFF_TOTAL (NSVC + NNODE + NPOD)

// ---- aggregation scratch layout (float) ----
#define AGG_SVC_OFF  ((size_t)0)
#define AGG_NODE_OFF ((size_t)NSVC * FD)
#define AGG_POD_OFF  ((size_t)(NSVC + NNODE) * FD)
#define AGG_TOTAL    ((size_t)(NSVC + NNODE + NPOD) * FD)

__device__ float g_agg[AGG_TOTAL];
__device__ int   g_deg[DEG_TOTAL];
__device__ float g_nrm[DEG_TOTAL];
__device__ int   g_off[OFF_TOTAL];
__device__ int   g_fill[OFF_TOTAL];
__device__ int   g_part[3 * 128];
__device__ int   g_eidx_svc[ESVC_MAX];
__device__ int   g_eidx_pn[EPN_MAX];
__device__ int   g_eidx_np[ENP_MAX];

// ============================================================
// K1: zero counters (deg + fill). agg no longer needs zeroing.
// ============================================================
__global__ void zero_kernel() {
    int stride = gridDim.x * blockDim.x;
    for (int i = blockIdx.x * blockDim.x + threadIdx.x; i < DEG_TOTAL; i += stride)
        g_deg[i] = 0;
    for (int i = blockIdx.x * blockDim.x + threadIdx.x; i < OFF_TOTAL; i += stride)
        g_fill[i] = 0;
}

// ============================================================
// K2: degree counting (src & dst) for one edge type
// ============================================================
__global__ void deg_kernel(const int* __restrict__ src, const int* __restrict__ dst,
                           int E, int off_s, int off_d) {
    int i = blockIdx.x * blockDim.x + threadIdx.x;
    if (i < E) {
        atomicAdd(&g_deg[off_s + src[i]], 1);
        atomicAdd(&g_deg[off_d + dst[i]], 1);
    }
}

// ============================================================
// K3: norms = rsqrt(max(deg,1)) for everything
// ============================================================
__global__ void nrm_kernel() {
    int i = blockIdx.x * blockDim.x + threadIdx.x;
    if (i < DEG_TOTAL) {
        int d = g_deg[i];
        g_nrm[i] = rsqrtf((float)(d > 1 ? d : 1));
    }
}

// ============================================================
// K4a/b/c: exclusive scan of dst degrees -> CSR row offsets
// ============================================================
__global__ void scan1(const int* __restrict__ deg, int n,
                      int* __restrict__ out, int* __restrict__ part) {
    __shared__ int s[1024];
    int t = threadIdx.x;
    int i = blockIdx.x * 1024 + t;
    int v = (i < n) ? deg[i] : 0;
    s[t] = v;
    __syncthreads();
    #pragma unroll
    for (int d = 1; d < 1024; d <<= 1) {
        int tv = (t >= d) ? s[t - d] : 0;
        __syncthreads();
        s[t] += tv;
        __syncthreads();
    }
    if (i < n) out[i] = s[t] - v;           // exclusive within block
    if (t == 1023) part[blockIdx.x] = s[t]; // block total
}

__global__ void scan2(int* part, int np) {
    __shared__ int s[128];
    int t = threadIdx.x;
    int v = (t < np) ? part[t] : 0;
    s[t] = v;
    __syncthreads();
    #pragma unroll
    for (int d = 1; d < 128; d <<= 1) {
        int tv = (t >= d) ? s[t - d] : 0;
        __syncthreads();
        s[t] += tv;
        __syncthreads();
    }
    if (t < np) part[t] = s[t] - v;         // exclusive over partials
}

__global__ void scan3(int* __restrict__ out, int n, const int* __restrict__ part) {
    int i = blockIdx.x * 1024 + threadIdx.x;
    if (i < n) out[i] += part[blockIdx.x];
}

// ============================================================
// K5: fill CSR edge lists (int atomics only)
// ============================================================
__global__ void fill_kernel(const int* __restrict__ src, const int* __restrict__ dst,
                            int E, const int* __restrict__ off,
                            int* __restrict__ fillc, int* __restrict__ eidx) {
    int i = blockIdx.x * blockDim.x + threadIdx.x;
    if (i < E) {
        int d = dst[i];
        int p = atomicAdd(&fillc[d], 1);
        eidx[off[d] + p] = src[i];
    }
}

// ============================================================
// K6: warp-per-dst-row gather + register accumulation
//     agg[d] = nd * sum_e ns[src_e] * x[src_e]
// ============================================================
__global__ void gather_kernel(const float* __restrict__ x,
                              const int* __restrict__ eidx,
                              const int* __restrict__ off,
                              const int* __restrict__ cnt,
                              const float* __restrict__ nsrc,
                              const float* __restrict__ ndst,
                              float* __restrict__ agg, int M) {
    int w = (blockIdx.x * blockDim.x + threadIdx.x) >> 5;
    int lane = threadIdx.x & 31;
    if (w >= M) return;
    int beg = off[w];
    int end = beg + cnt[w];
    const float4* x4 = reinterpret_cast<const float4*>(x);

    float4 acc = make_float4(0.f, 0.f, 0.f, 0.f);
    int e = beg;
    for (; e + 4 <= end; e += 4) {
        int s0 = __ldg(eidx + e + 0);
        int s1 = __ldg(eidx + e + 1);
        int s2 = __ldg(eidx + e + 2);
        int s3 = __ldg(eidx + e + 3);
        float n0 = __ldg(nsrc + s0);
        float n1 = __ldg(nsrc + s1);
        float n2 = __ldg(nsrc + s2);
        float n3 = __ldg(nsrc + s3);
        float4 v0 = x4[(size_t)s0 * 32 + lane];
        float4 v1 = x4[(size_t)s1 * 32 + lane];
        float4 v2 = x4[(size_t)s2 * 32 + lane];
        float4 v3 = x4[(size_t)s3 * 32 + lane];
        acc.x += v0.x * n0; acc.y += v0.y * n0; acc.z += v0.z * n0; acc.w += v0.w * n0;
        acc.x += v1.x * n1; acc.y += v1.y * n1; acc.z += v1.z * n1; acc.w += v1.w * n1;
        acc.x += v2.x * n2; acc.y += v2.y * n2; acc.z += v2.z * n2; acc.w += v2.w * n2;
        acc.x += v3.x * n3; acc.y += v3.y * n3; acc.z += v3.z * n3; acc.w += v3.w * n3;
    }
    for (; e < end; e++) {
        int s0 = __ldg(eidx + e);
        float n0 = __ldg(nsrc + s0);
        float4 v0 = x4[(size_t)s0 * 32 + lane];
        acc.x += v0.x * n0; acc.y += v0.y * n0; acc.z += v0.z * n0; acc.w += v0.w * n0;
    }
    float nd = ndst[w];
    reinterpret_cast<float4*>(agg)[(size_t)w * 32 + lane] =
        make_float4(acc.x * nd, acc.y * nd, acc.z * nd, acc.w * nd);
}

// ============================================================
// K7: fused per-type epilogue:
//     out = leaky( agg @ W1 + b1 ) @ W2 + b2   (agg already normalized)
// ============================================================
#define GEMM_SMEM_FLOATS (128*128 + 128*64 + 128*129 + 128 + 64)

__global__ void gemm_fused(size_t agg_off,
                           const float* __restrict__ W1, const float* __restrict__ b1,
                           const float* __restrict__ W2, const float* __restrict__ b2,
                           float* __restrict__ out, int M) {
    extern __shared__ float sm[];
    float* W1s = sm;                    // 128*128
    float* W2s = W1s + 128 * 128;       // 128*64
    float* As  = W2s + 128 * 64;        // 128*129 (padded)
    float* b1s = As + 128 * 129;        // 128
    float* b2s = b1s + 128;             // 64

    int tid = threadIdx.x;  // 128 threads

    {
        const float4* s4 = reinterpret_cast<const float4*>(W1);
        float4* d4 = reinterpret_cast<float4*>(W1s);
        #pragma unroll
        for (int i = 0; i < 32; i++) d4[i * 128 + tid] = s4[i * 128 + tid];
    }
    {
        const float4* s4 = reinterpret_cast<const float4*>(W2);
        float4* d4 = reinterpret_cast<float4*>(W2s);
        #pragma unroll
        for (int i = 0; i < 16; i++) d4[i * 128 + tid] = s4[i * 128 + tid];
    }
    b1s[tid] = b1[tid];
    if (tid < 64) b2s[tid] = b2[tid];

    int row0 = blockIdx.x * 128;
    int row  = row0 + tid;

    // cooperative, coalesced A-tile load (agg already fully normalized)
    const float4* av = reinterpret_cast<const float4*>(g_agg + agg_off);
    #pragma unroll
    for (int it = 0; it < 32; it++) {
        int f4i = it * 128 + tid;
        int r = f4i >> 5, c = f4i & 31;
        float4 v = make_float4(0.f, 0.f, 0.f, 0.f);
        if (row0 + r < M) v = av[(size_t)(row0 + r) * 32 + c];
        float* dp = As + r * 129 + c * 4;
        dp[0] = v.x; dp[1] = v.y; dp[2] = v.z; dp[3] = v.w;
    }
    __syncthreads();

    if (row >= M) return;

    float o[64];
    #pragma unroll
    for (int n = 0; n < 64; n++) o[n] = b2s[n];

    const float* arow = As + tid * 129;

    #pragma unroll
    for (int c = 0; c < 4; c++) {            // hidden columns in chunks of 32
        float h[32];
        #pragma unroll
        for (int j = 0; j < 32; j++) h[j] = b1s[c * 32 + j];

        #pragma unroll 4
        for (int k = 0; k < 128; k++) {
            float a = arow[k];
            const float4* wr = reinterpret_cast<const float4*>(W1s + k * 128 + c * 32);
            #pragma unroll
            for (int j4 = 0; j4 < 8; j4++) {
                float4 w = wr[j4];
                h[j4 * 4 + 0] += a * w.x;
                h[j4 * 4 + 1] += a * w.y;
                h[j4 * 4 + 2] += a * w.z;
                h[j4 * 4 + 3] += a * w.w;
            }
        }
        #pragma unroll
        for (int j = 0; j < 32; j++) {
            float hv = h[j];
            float lh = hv > 0.f ? hv : 0.01f * hv;
            const float4* w2r = reinterpret_cast<const float4*>(W2s + (c * 32 + j) * 64);
            #pragma unroll
            for (int n4 = 0; n4 < 16; n4++) {
                float4 w = w2r[n4];
                o[n4 * 4 + 0] += lh * w.x;
                o[n4 * 4 + 1] += lh * w.y;
                o[n4 * 4 + 2] += lh * w.z;
                o[n4 * 4 + 3] += lh * w.w;
            }
        }
    }

    float4* ov = reinterpret_cast<float4*>(out) + (size_t)row * 16;
    #pragma unroll
    for (int n4 = 0; n4 < 16; n4++)
        ov[n4] = make_float4(o[n4 * 4], o[n4 * 4 + 1], o[n4 * 4 + 2], o[n4 * 4 + 3]);
}

// ============================================================
// launch
// ============================================================
static inline int* dev_ptr_int(int* sym_base, int off) { return sym_base + off; }

extern "C" void kernel_launch(void* const* d_in, const int* in_sizes, int n_in,
                              void* d_out, int out_size) {
    const float* x_svc  = (const float*)d_in[0];
    const float* x_pod  = (const float*)d_in[1];
    const float* x_node = (const float*)d_in[2];
    const int* svc_src = (const int*)d_in[3];
    const int* svc_dst = (const int*)d_in[4];
    const int* pn_src  = (const int*)d_in[5];
    const int* pn_dst  = (const int*)d_in[6];
    const int* np_src  = (const int*)d_in[7];
    const int* np_dst  = (const int*)d_in[8];
    const float* W_call = (const float*)d_in[9];
    const float* b_call = (const float*)d_in[10];
    const float* W_in   = (const float*)d_in[11];
    const float* b_in   = (const float*)d_in[12];
    const float* W_ni   = (const float*)d_in[13];
    const float* b_ni   = (const float*)d_in[14];
    const float* W_lin_svc  = (const float*)d_in[15];
    const float* b_lin_svc  = (const float*)d_in[16];
    const float* W_lin_node = (const float*)d_in[17];
    const float* b_lin_node = (const float*)d_in[18];
    const float* W_lin_pod  = (const float*)d_in[19];
    const float* b_lin_pod  = (const float*)d_in[20];
    float* out = (float*)d_out;

    int E_svc = in_sizes[3];
    int E_pn  = in_sizes[5];
    int E_np  = in_sizes[7];

    // device symbol addresses (host-side pointers into __device__ globals)
    int *p_deg, *p_off, *p_fill, *p_part, *p_esvc, *p_epn, *p_enp;
    float *p_nrm, *p_agg;
    cudaGetSymbolAddress((void**)&p_deg,  g_deg);
    cudaGetSymbolAddress((void**)&p_off,  g_off);
    cudaGetSymbolAddress((void**)&p_fill, g_fill);
    cudaGetSymbolAddress((void**)&p_part, g_part);
    cudaGetSymbolAddress((void**)&p_esvc, g_eidx_svc);
    cudaGetSymbolAddress((void**)&p_epn,  g_eidx_pn);
    cudaGetSymbolAddress((void**)&p_enp,  g_eidx_np);
    cudaGetSymbolAddress((void**)&p_nrm,  g_nrm);
    cudaGetSymbolAddress((void**)&p_agg,  g_agg);

    size_t smem = GEMM_SMEM_FLOATS * sizeof(float);
    cudaFuncSetAttribute(gemm_fused, cudaFuncAttributeMaxDynamicSharedMemorySize, (int)smem);

    zero_kernel<<<256, 256>>>();

    deg_kernel<<<(E_svc + 255) / 256, 256>>>(svc_src, svc_dst, E_svc, DEG_SVC_SRC, DEG_SVC_DST);
    deg_kernel<<<(E_pn  + 255) / 256, 256>>>(pn_src,  pn_dst,  E_pn,  DEG_PN_SRC,  DEG_PN_DST);
    deg_kernel<<<(E_np  + 255) / 256, 256>>>(np_src,  np_dst,  E_np,  DEG_NP_SRC,  DEG_NP_DST);

    nrm_kernel<<<(DEG_TOTAL + 255) / 256, 256>>>();

    // CSR offsets per type (exclusive scan of dst degrees)
    int nb_svc  = (NSVC  + 1023) / 1024;
    int nb_node = (NNODE + 1023) / 1024;
    int nb_pod  = (NPOD  + 1023) / 1024;
    scan1<<<nb_svc,  1024>>>(p_deg + DEG_SVC_DST, NSVC,  p_off + OFF_SVC,  p_part + 0);
    scan1<<<nb_node, 1024>>>(p_deg + DEG_PN_DST,  NNODE, p_off + OFF_NODE, p_part + 128);
    scan1<<<nb_pod,  1024>>>(p_deg + DEG_NP_DST,  NPOD,  p_off + OFF_POD,  p_part + 256);
    scan2<<<1, 128>>>(p_part + 0,   nb_svc);
    scan2<<<1, 128>>>(p_part + 128, nb_node);
    scan2<<<1, 128>>>(p_part + 256, nb_pod);
    scan3<<<nb_svc,  1024>>>(p_off + OFF_SVC,  NSVC,  p_part + 0);
    scan3<<<nb_node, 1024>>>(p_off + OFF_NODE, NNODE, p_part + 128);
    scan3<<<nb_pod,  1024>>>(p_off + OFF_POD,  NPOD,  p_part + 256);

    // fill CSR edge lists
    fill_kernel<<<(E_svc + 255) / 256, 256>>>(svc_src, svc_dst, E_svc,
                                              p_off + OFF_SVC,  p_fill + OFF_SVC,  p_esvc);
    fill_kernel<<<(E_pn  + 255) / 256, 256>>>(pn_src,  pn_dst,  E_pn,
                                              p_off + OFF_NODE, p_fill + OFF_NODE, p_epn);
    fill_kernel<<<(E_np  + 255) / 256, 256>>>(np_src,  np_dst,  E_np,
                                              p_off + OFF_POD,  p_fill + OFF_POD,  p_enp);

    // gather: warp per dst row
    gather_kernel<<<(NSVC  + 7) / 8, 256>>>(x_svc,  p_esvc, p_off + OFF_SVC,
                                            p_deg + DEG_SVC_DST, p_nrm + DEG_SVC_SRC,
                                            p_nrm + DEG_SVC_DST, p_agg + AGG_SVC_OFF, NSVC);
    gather_kernel<<<(NNODE + 7) / 8, 256>>>(x_pod,  p_epn,  p_off + OFF_NODE,
                                            p_deg + DEG_PN_DST,  p_nrm + DEG_PN_SRC,
                                            p_nrm + DEG_PN_DST,  p_agg + AGG_NODE_OFF, NNODE);
    gather_kernel<<<(NPOD  + 7) / 8, 256>>>(x_node, p_enp,  p_off + OFF_POD,
                                            p_deg + DEG_NP_DST,  p_nrm + DEG_NP_SRC,
                                            p_nrm + DEG_NP_DST,  p_agg + AGG_POD_OFF, NPOD);

    // fused GEMM epilogue per node type, writing concat slices
    gemm_fused<<<(NSVC  + 127) / 128, 128, smem>>>(AGG_SVC_OFF,  W_call, b_call,
                                                   W_lin_svc,  b_lin_svc,  out, NSVC);
    gemm_fused<<<(NNODE + 127) / 128, 128, smem>>>(AGG_NODE_OFF, W_in,   b_in,
                                                   W_lin_node, b_lin_node, out + (size_t)NSVC * OUTD, NNODE);
    gemm_fused<<<(NPOD  + 127) / 128, 128, smem>>>(AGG_POD_OFF,  W_ni,   b_ni,
                                                   W_lin_pod,  b_lin_pod,  out + (size_t)(NSVC + NNODE) * OUTD, NPOD);
}

// round 4
// speedup vs baseline: 2.7312x; 1.6749x over previous
#include <cuda_runtime.h>
#include <cuda_bf16.h>
#include <cstdint>

#define NSVC 50000
#define NNODE 20000
#define NPOD 100000
#define FD 128
#define OUTD 64
#define ESVC_MAX 1600000
#define EPN_MAX  100000
#define ENP_MAX  100000

// ---- degree/norm array layout ----
#define DEG_SVC_SRC 0
#define DEG_SVC_DST (NSVC)
#define DEG_PN_SRC  (2*NSVC)
#define DEG_PN_DST  (2*NSVC + NPOD)
#define DEG_NP_SRC  (2*NSVC + NPOD + NNODE)
#define DEG_NP_DST  (2*NSVC + NPOD + 2*NNODE)
#define DEG_TOTAL   (2*NSVC + 2*NPOD + 2*NNODE)

#define OFF_SVC  0
#define OFF_NODE (NSVC)
#define OFF_POD  (NSVC + NNODE)
#define OFF_TOTAL (NSVC + NNODE + NPOD)

#define AGG_SVC_OFF  ((size_t)0)
#define AGG_NODE_OFF ((size_t)NSVC * FD)
#define AGG_POD_OFF  ((size_t)(NSVC + NNODE) * FD)
#define AGG_TOTAL    ((size_t)(NSVC + NNODE + NPOD) * FD)

__device__ float g_agg[AGG_TOTAL];
__device__ int   g_deg[DEG_TOTAL];
__device__ float g_nrm[DEG_TOTAL];
__device__ int   g_off[OFF_TOTAL];
__device__ int   g_fill[OFF_TOTAL];
__device__ int   g_part[3 * 128];
__device__ int   g_eidx_svc[ESVC_MAX];
__device__ int   g_eidx_pn[EPN_MAX];
__device__ int   g_eidx_np[ENP_MAX];

// pre-split transposed weights, plain [n][k] row-major bf16, per type
__device__ __nv_bfloat16 g_w1hi[3][128 * 128];
__device__ __nv_bfloat16 g_w1lo[3][128 * 128];
__device__ __nv_bfloat16 g_w2hi[3][64 * 128];
__device__ __nv_bfloat16 g_w2lo[3][64 * 128];

// ============================================================
// prep kernels (unchanged from R2 — R2 passed with these)
// ============================================================
__global__ void zero_kernel() {
    int stride = gridDim.x * blockDim.x;
    for (int i = blockIdx.x * blockDim.x + threadIdx.x; i < DEG_TOTAL; i += stride)
        g_deg[i] = 0;
    for (int i = blockIdx.x * blockDim.x + threadIdx.x; i < OFF_TOTAL; i += stride)
        g_fill[i] = 0;
}

__global__ void deg_kernel(const int* __restrict__ src, const int* __restrict__ dst,
                           int E, int off_s, int off_d) {
    int i = blockIdx.x * blockDim.x + threadIdx.x;
    if (i < E) {
        atomicAdd(&g_deg[off_s + src[i]], 1);
        atomicAdd(&g_deg[off_d + dst[i]], 1);
    }
}

__global__ void nrm_kernel() {
    int i = blockIdx.x * blockDim.x + threadIdx.x;
    if (i < DEG_TOTAL) {
        int d = g_deg[i];
        g_nrm[i] = rsqrtf((float)(d > 1 ? d : 1));
    }
}

__global__ void scan1(const int* __restrict__ deg, int n,
                      int* __restrict__ out, int* __restrict__ part) {
    __shared__ int s[1024];
    int t = threadIdx.x;
    int i = blockIdx.x * 1024 + t;
    int v = (i < n) ? deg[i] : 0;
    s[t] = v;
    __syncthreads();
    #pragma unroll
    for (int d = 1; d < 1024; d <<= 1) {
        int tv = (t >= d) ? s[t - d] : 0;
        __syncthreads();
        s[t] += tv;
        __syncthreads();
    }
    if (i < n) out[i] = s[t] - v;
    if (t == 1023) part[blockIdx.x] = s[t];
}

__global__ void scan2(int* part, int np) {
    __shared__ int s[128];
    int t = threadIdx.x;
    int v = (t < np) ? part[t] : 0;
    s[t] = v;
    __syncthreads();
    #pragma unroll
    for (int d = 1; d < 128; d <<= 1) {
        int tv = (t >= d) ? s[t - d] : 0;
        __syncthreads();
        s[t] += tv;
        __syncthreads();
    }
    if (t < np) part[t] = s[t] - v;
}

__global__ void scan3(int* __restrict__ out, int n, const int* __restrict__ part) {
    int i = blockIdx.x * 1024 + threadIdx.x;
    if (i < n) out[i] += part[blockIdx.x];
}

__global__ void fill_kernel(const int* __restrict__ src, const int* __restrict__ dst,
                            int E, const int* __restrict__ off,
                            int* __restrict__ fillc, int* __restrict__ eidx) {
    int i = blockIdx.x * blockDim.x + threadIdx.x;
    if (i < E) {
        int d = dst[i];
        int p = atomicAdd(&fillc[d], 1);
        eidx[off[d] + p] = src[i];
    }
}

__global__ void gather_kernel(const float* __restrict__ x,
                              const int* __restrict__ eidx,
                              const int* __restrict__ off,
                              const int* __restrict__ cnt,
                              const float* __restrict__ nsrc,
                              const float* __restrict__ ndst,
                              float* __restrict__ agg, int M) {
    int w = (blockIdx.x * blockDim.x + threadIdx.x) >> 5;
    int lane = threadIdx.x & 31;
    if (w >= M) return;
    int beg = off[w];
    int end = beg + cnt[w];
    const float4* x4 = reinterpret_cast<const float4*>(x);

    float4 acc = make_float4(0.f, 0.f, 0.f, 0.f);
    int e = beg;
    for (; e + 4 <= end; e += 4) {
        int s0 = __ldg(eidx + e + 0);
        int s1 = __ldg(eidx + e + 1);
        int s2 = __ldg(eidx + e + 2);
        int s3 = __ldg(eidx + e + 3);
        float n0 = __ldg(nsrc + s0);
        float n1 = __ldg(nsrc + s1);
        float n2 = __ldg(nsrc + s2);
        float n3 = __ldg(nsrc + s3);
        float4 v0 = x4[(size_t)s0 * 32 + lane];
        float4 v1 = x4[(size_t)s1 * 32 + lane];
        float4 v2 = x4[(size_t)s2 * 32 + lane];
        float4 v3 = x4[(size_t)s3 * 32 + lane];
        acc.x += v0.x * n0; acc.y += v0.y * n0; acc.z += v0.z * n0; acc.w += v0.w * n0;
        acc.x += v1.x * n1; acc.y += v1.y * n1; acc.z += v1.z * n1; acc.w += v1.w * n1;
        acc.x += v2.x * n2; acc.y += v2.y * n2; acc.z += v2.z * n2; acc.w += v2.w * n2;
        acc.x += v3.x * n3; acc.y += v3.y * n3; acc.z += v3.z * n3; acc.w += v3.w * n3;
    }
    for (; e < end; e++) {
        int s0 = __ldg(eidx + e);
        float n0 = __ldg(nsrc + s0);
        float4 v0 = x4[(size_t)s0 * 32 + lane];
        acc.x += v0.x * n0; acc.y += v0.y * n0; acc.z += v0.z * n0; acc.w += v0.w * n0;
    }
    float nd = ndst[w];
    reinterpret_cast<float4*>(agg)[(size_t)w * 32 + lane] =
        make_float4(acc.x * nd, acc.y * nd, acc.z * nd, acc.w * nd);
}

// ============================================================
// Weight conversion: fp32 W -> transposed bf16 hi/lo, plain [n][k]
// ============================================================
__global__ void convw_kernel(const float* __restrict__ W1, const float* __restrict__ W2,
                             __nv_bfloat16* __restrict__ w1hi, __nv_bfloat16* __restrict__ w1lo,
                             __nv_bfloat16* __restrict__ w2hi, __nv_bfloat16* __restrict__ w2lo) {
    int n = threadIdx.x;  // 128 threads
    for (int k = 0; k < 128; k++) {
        float v = W1[k * 128 + n];
        __nv_bfloat16 hi = __float2bfloat16(v);
        __nv_bfloat16 lo = __float2bfloat16(v - __bfloat162float(hi));
        w1hi[n * 128 + k] = hi;
        w1lo[n * 128 + k] = lo;
    }
    if (n < 64) {
        for (int k = 0; k < 128; k++) {
            float v = W2[k * 64 + n];
            __nv_bfloat16 hi = __float2bfloat16(v);
            __nv_bfloat16 lo = __float2bfloat16(v - __bfloat162float(hi));
            w2hi[n * 128 + k] = hi;
            w2lo[n * 128 + k] = lo;
        }
    }
}

// ============================================================
// mma.sync bf16 fused GEMM kernel (base-target tensor path)
//   D1 = Ahi@W1hi + Alo@W1hi + Ahi@W1lo
//   h  = leaky(D1 + b1) -> bf16 hi/lo (written back over A)
//   D2 = hhi@W2hi + hlo@W2hi + hhi@W2lo ; out = D2 + b2
// block: 256 threads (8 warps), one 128-row tile, 1 block/SM.
// smem rows padded to 136 bf16 (272B) -> conflict-free fragment LDS.
// ============================================================
#define SROW 136
#define SROWB 272
#define SM_A_HI 0
#define SM_A_LO 34816
#define SM_W1HI 69632
#define SM_W1LO 104448
#define SM_W2HI 139264
#define SM_W2LO 156672
#define SM_B1   174080
#define SM_B2   174592
#define SM_TOTAL 174848

__device__ __forceinline__ uint32_t pack_bf2(__nv_bfloat16 a, __nv_bfloat16 b) {
    return (uint32_t)__bfloat16_as_ushort(a) | ((uint32_t)__bfloat16_as_ushort(b) << 16);
}
__device__ __forceinline__ void split_bf(float v, __nv_bfloat16& hi, __nv_bfloat16& lo) {
    hi = __float2bfloat16(v);
    lo = __float2bfloat16(v - __bfloat162float(hi));
}
__device__ __forceinline__ void mma_bf16(float* c, uint32_t a0, uint32_t a1,
                                         uint32_t a2, uint32_t a3,
                                         uint32_t b0, uint32_t b1) {
    asm volatile(
        "mma.sync.aligned.m16n8k16.row.col.f32.bf16.bf16.f32 "
        "{%0,%1,%2,%3}, {%4,%5,%6,%7}, {%8,%9}, {%0,%1,%2,%3};"
        : "+f"(c[0]), "+f"(c[1]), "+f"(c[2]), "+f"(c[3])
        : "r"(a0), "r"(a1), "r"(a2), "r"(a3), "r"(b0), "r"(b1));
}
__device__ __forceinline__ uint32_t lds_u32(const char* base, int row, int col) {
    return *(const uint32_t*)(base + row * SROWB + col * 2);
}

__global__ void __launch_bounds__(256, 1)
gemm_tc(const float* __restrict__ agg,
        const __nv_bfloat16* __restrict__ w1hi, const __nv_bfloat16* __restrict__ w1lo,
        const __nv_bfloat16* __restrict__ w2hi, const __nv_bfloat16* __restrict__ w2lo,
        const float* __restrict__ b1, const float* __restrict__ b2,
        float* __restrict__ out, int M) {
    extern __shared__ char sm[];
    int tid = threadIdx.x;
    int wid = tid >> 5;
    int lane = tid & 31;
    int g = lane >> 2;       // group 0..7
    int tig = lane & 3;      // thread-in-group

    // ---- stage weights into padded smem ----
    {
        const uint4* s1h = (const uint4*)w1hi;
        const uint4* s1l = (const uint4*)w1lo;
        #pragma unroll
        for (int i = 0; i < 8; i++) {
            int idx = i * 256 + tid;        // 2048 uint4 = 128 rows x 16
            int row = idx >> 4, gq = idx & 15;
            *(uint4*)(sm + SM_W1HI + row * SROWB + gq * 16) = s1h[idx];
            *(uint4*)(sm + SM_W1LO + row * SROWB + gq * 16) = s1l[idx];
        }
        const uint4* s2h = (const uint4*)w2hi;
        const uint4* s2l = (const uint4*)w2lo;
        #pragma unroll
        for (int i = 0; i < 4; i++) {
            int idx = i * 256 + tid;        // 1024 uint4 = 64 rows x 16
            int row = idx >> 4, gq = idx & 15;
            *(uint4*)(sm + SM_W2HI + row * SROWB + gq * 16) = s2h[idx];
            *(uint4*)(sm + SM_W2LO + row * SROWB + gq * 16) = s2l[idx];
        }
    }
    if (tid < 128) ((float*)(sm + SM_B1))[tid] = b1[tid];
    else if (tid < 192) ((float*)(sm + SM_B2))[tid - 128] = b2[tid - 128];

    // ---- load + split A tile: thread handles half a row ----
    {
        int row = tid >> 1;
        int half = (tid & 1) * 64;
        int grow = blockIdx.x * 128 + row;
        const float4* av = (const float4*)agg + (size_t)grow * 32 + (half >> 2);
        #pragma unroll
        for (int j = 0; j < 16; j++) {
            float4 v = (grow < M) ? av[j] : make_float4(0.f, 0.f, 0.f, 0.f);
            __nv_bfloat16 h0, h1, h2, h3, l0, l1, l2, l3;
            split_bf(v.x, h0, l0); split_bf(v.y, h1, l1);
            split_bf(v.z, h2, l2); split_bf(v.w, h3, l3);
            int col = half + j * 4;
            *(uint2*)(sm + SM_A_HI + row * SROWB + col * 2) =
                make_uint2(pack_bf2(h0, h1), pack_bf2(h2, h3));
            *(uint2*)(sm + SM_A_LO + row * SROWB + col * 2) =
                make_uint2(pack_bf2(l0, l1), pack_bf2(l2, l3));
        }
    }
    __syncthreads();

    int mtb = (wid & 3) * 2;          // 2 m-tiles (32 rows) per warp
    int nb1 = (wid >> 2) * 64;        // GEMM1 col half

    // ---- GEMM1 ----
    float acc[2][8][4];
    #pragma unroll
    for (int mt = 0; mt < 2; mt++)
        #pragma unroll
        for (int nt = 0; nt < 8; nt++)
            #pragma unroll
            for (int q = 0; q < 4; q++) acc[mt][nt][q] = 0.f;

    #pragma unroll
    for (int kc = 0; kc < 8; kc++) {
        int k0 = kc * 16 + tig * 2;
        uint32_t ah[2][4], al[2][4];
        #pragma unroll
        for (int mt = 0; mt < 2; mt++) {
            int r = (mtb + mt) * 16 + g;
            ah[mt][0] = lds_u32(sm + SM_A_HI, r,     k0);
            ah[mt][1] = lds_u32(sm + SM_A_HI, r + 8, k0);
            ah[mt][2] = lds_u32(sm + SM_A_HI, r,     k0 + 8);
            ah[mt][3] = lds_u32(sm + SM_A_HI, r + 8, k0 + 8);
            al[mt][0] = lds_u32(sm + SM_A_LO, r,     k0);
            al[mt][1] = lds_u32(sm + SM_A_LO, r + 8, k0);
            al[mt][2] = lds_u32(sm + SM_A_LO, r,     k0 + 8);
            al[mt][3] = lds_u32(sm + SM_A_LO, r + 8, k0 + 8);
        }
        #pragma unroll
        for (int nt = 0; nt < 8; nt++) {
            int n = nb1 + nt * 8 + g;
            uint32_t bh0 = lds_u32(sm + SM_W1HI, n, k0);
            uint32_t bh1 = lds_u32(sm + SM_W1HI, n, k0 + 8);
            uint32_t bl0 = lds_u32(sm + SM_W1LO, n, k0);
            uint32_t bl1 = lds_u32(sm + SM_W1LO, n, k0 + 8);
            #pragma unroll
            for (int mt = 0; mt < 2; mt++) {
                mma_bf16(acc[mt][nt], ah[mt][0], ah[mt][1], ah[mt][2], ah[mt][3], bh0, bh1);
                mma_bf16(acc[mt][nt], al[mt][0], al[mt][1], al[mt][2], al[mt][3], bh0, bh1);
                mma_bf16(acc[mt][nt], ah[mt][0], ah[mt][1], ah[mt][2], ah[mt][3], bl0, bl1);
            }
        }
    }
    __syncthreads();   // all GEMM1 reads of A done before h overwrites A

    // ---- epilogue1: bias + leaky + re-split, h -> A buffers ----
    {
        const float* b1s = (const float*)(sm + SM_B1);
        #pragma unroll
        for (int mt = 0; mt < 2; mt++) {
            #pragma unroll
            for (int nt = 0; nt < 8; nt++) {
                int row = (mtb + mt) * 16 + g;
                int col = nb1 + nt * 8 + tig * 2;
                float bb0 = b1s[col], bb1 = b1s[col + 1];
                float v0 = acc[mt][nt][0] + bb0;
                float v1 = acc[mt][nt][1] + bb1;
                float v2 = acc[mt][nt][2] + bb0;
                float v3 = acc[mt][nt][3] + bb1;
                v0 = v0 > 0.f ? v0 : 0.01f * v0;
                v1 = v1 > 0.f ? v1 : 0.01f * v1;
                v2 = v2 > 0.f ? v2 : 0.01f * v2;
                v3 = v3 > 0.f ? v3 : 0.01f * v3;
                __nv_bfloat16 h0, h1, h2, h3, l0, l1, l2, l3;
                split_bf(v0, h0, l0); split_bf(v1, h1, l1);
                split_bf(v2, h2, l2); split_bf(v3, h3, l3);
                *(uint32_t*)(sm + SM_A_HI + row * SROWB + col * 2) = pack_bf2(h0, h1);
                *(uint32_t*)(sm + SM_A_LO + row * SROWB + col * 2) = pack_bf2(l0, l1);
                *(uint32_t*)(sm + SM_A_HI + (row + 8) * SROWB + col * 2) = pack_bf2(h2, h3);
                *(uint32_t*)(sm + SM_A_LO + (row + 8) * SROWB + col * 2) = pack_bf2(l2, l3);
            }
        }
    }
    __syncthreads();

    // ---- GEMM2 ----
    int nb2 = (wid >> 2) * 32;
    float acc2[2][4][4];
    #pragma unroll
    for (int mt = 0; mt < 2; mt++)
        #pragma unroll
        for (int nt = 0; nt < 4; nt++)
            #pragma unroll
            for (int q = 0; q < 4; q++) acc2[mt][nt][q] = 0.f;

    #pragma unroll
    for (int kc = 0; kc < 8; kc++) {
        int k0 = kc * 16 + tig * 2;
        uint32_t ah[2][4], al[2][4];
        #pragma unroll
        for (int mt = 0; mt < 2; mt++) {
            int r = (mtb + mt) * 16 + g;
            ah[mt][0] = lds_u32(sm + SM_A_HI, r,     k0);
            ah[mt][1] = lds_u32(sm + SM_A_HI, r + 8, k0);
            ah[mt][2] = lds_u32(sm + SM_A_HI, r,     k0 + 8);
            ah[mt][3] = lds_u32(sm + SM_A_HI, r + 8, k0 + 8);
            al[mt][0] = lds_u32(sm + SM_A_LO, r,     k0);
            al[mt][1] = lds_u32(sm + SM_A_LO, r + 8, k0);
            al[mt][2] = lds_u32(sm + SM_A_LO, r,     k0 + 8);
            al[mt][3] = lds_u32(sm + SM_A_LO, r + 8, k0 + 8);
        }
        #pragma unroll
        for (int nt = 0; nt < 4; nt++) {
            int n = nb2 + nt * 8 + g;
            uint32_t bh0 = lds_u32(sm + SM_W2HI, n, k0);
            uint32_t bh1 = lds_u32(sm + SM_W2HI, n, k0 + 8);
            uint32_t bl0 = lds_u32(sm + SM_W2LO, n, k0);
            uint32_t bl1 = lds_u32(sm + SM_W2LO, n, k0 + 8);
            #pragma unroll
            for (int mt = 0; mt < 2; mt++) {
                mma_bf16(acc2[mt][nt], ah[mt][0], ah[mt][1], ah[mt][2], ah[mt][3], bh0, bh1);
                mma_bf16(acc2[mt][nt], al[mt][0], al[mt][1], al[mt][2], al[mt][3], bh0, bh1);
                mma_bf16(acc2[mt][nt], ah[mt][0], ah[mt][1], ah[mt][2], ah[mt][3], bl0, bl1);
            }
        }
    }

    // ---- epilogue2: bias + store ----
    {
        const float* b2s = (const float*)(sm + SM_B2);
        #pragma unroll
        for (int mt = 0; mt < 2; mt++) {
            #pragma unroll
            for (int nt = 0; nt < 4; nt++) {
                int row = blockIdx.x * 128 + (mtb + mt) * 16 + g;
                int col = nb2 + nt * 8 + tig * 2;
                float bb0 = b2s[col], bb1 = b2s[col + 1];
                if (row < M)
                    *(float2*)(out + (size_t)row * 64 + col) =
                        make_float2(acc2[mt][nt][0] + bb0, acc2[mt][nt][1] + bb1);
                if (row + 8 < M)
                    *(float2*)(out + (size_t)(row + 8) * 64 + col) =
                        make_float2(acc2[mt][nt][2] + bb0, acc2[mt][nt][3] + bb1);
            }
        }
    }
}

// ============================================================
// launch
// ============================================================
extern "C" void kernel_launch(void* const* d_in, const int* in_sizes, int n_in,
                              void* d_out, int out_size) {
    const float* x_svc  = (const float*)d_in[0];
    const float* x_pod  = (const float*)d_in[1];
    const float* x_node = (const float*)d_in[2];
    const int* svc_src = (const int*)d_in[3];
    const int* svc_dst = (const int*)d_in[4];
    const int* pn_src  = (const int*)d_in[5];
    const int* pn_dst  = (const int*)d_in[6];
    const int* np_src  = (const int*)d_in[7];
    const int* np_dst  = (const int*)d_in[8];
    const float* W_call = (const float*)d_in[9];
    const float* b_call = (const float*)d_in[10];
    const float* W_in   = (const float*)d_in[11];
    const float* b_in   = (const float*)d_in[12];
    const float* W_ni   = (const float*)d_in[13];
    const float* b_ni   = (const float*)d_in[14];
    const float* W_lin_svc  = (const float*)d_in[15];
    const float* b_lin_svc  = (const float*)d_in[16];
    const float* W_lin_node = (const float*)d_in[17];
    const float* b_lin_node = (const float*)d_in[18];
    const float* W_lin_pod  = (const float*)d_in[19];
    const float* b_lin_pod  = (const float*)d_in[20];
    float* out = (float*)d_out;

    int E_svc = in_sizes[3];
    int E_pn  = in_sizes[5];
    int E_np  = in_sizes[7];

    int *p_deg, *p_off, *p_fill, *p_part, *p_esvc, *p_epn, *p_enp;
    float *p_nrm, *p_agg;
    __nv_bfloat16 *p_w1hi, *p_w1lo, *p_w2hi, *p_w2lo;
    cudaGetSymbolAddress((void**)&p_deg,  g_deg);
    cudaGetSymbolAddress((void**)&p_off,  g_off);
    cudaGetSymbolAddress((void**)&p_fill, g_fill);
    cudaGetSymbolAddress((void**)&p_part, g_part);
    cudaGetSymbolAddress((void**)&p_esvc, g_eidx_svc);
    cudaGetSymbolAddress((void**)&p_epn,  g_eidx_pn);
    cudaGetSymbolAddress((void**)&p_enp,  g_eidx_np);
    cudaGetSymbolAddress((void**)&p_nrm,  g_nrm);
    cudaGetSymbolAddress((void**)&p_agg,  g_agg);
    cudaGetSymbolAddress((void**)&p_w1hi, g_w1hi);
    cudaGetSymbolAddress((void**)&p_w1lo, g_w1lo);
    cudaGetSymbolAddress((void**)&p_w2hi, g_w2hi);
    cudaGetSymbolAddress((void**)&p_w2lo, g_w2lo);

    cudaFuncSetAttribute(gemm_tc, cudaFuncAttributeMaxDynamicSharedMemorySize, SM_TOTAL);

    zero_kernel<<<256, 256>>>();

    convw_kernel<<<1, 128>>>(W_call, W_lin_svc,  p_w1hi + 0 * 16384, p_w1lo + 0 * 16384,
                             p_w2hi + 0 * 8192,  p_w2lo + 0 * 8192);
    convw_kernel<<<1, 128>>>(W_in,   W_lin_node, p_w1hi + 1 * 16384, p_w1lo + 1 * 16384,
                             p_w2hi + 1 * 8192,  p_w2lo + 1 * 8192);
    convw_kernel<<<1, 128>>>(W_ni,   W_lin_pod,  p_w1hi + 2 * 16384, p_w1lo + 2 * 16384,
                             p_w2hi + 2 * 8192,  p_w2lo + 2 * 8192);

    deg_kernel<<<(E_svc + 255) / 256, 256>>>(svc_src, svc_dst, E_svc, DEG_SVC_SRC, DEG_SVC_DST);
    deg_kernel<<<(E_pn  + 255) / 256, 256>>>(pn_src,  pn_dst,  E_pn,  DEG_PN_SRC,  DEG_PN_DST);
    deg_kernel<<<(E_np  + 255) / 256, 256>>>(np_src,  np_dst,  E_np,  DEG_NP_SRC,  DEG_NP_DST);

    nrm_kernel<<<(DEG_TOTAL + 255) / 256, 256>>>();

    int nb_svc  = (NSVC  + 1023) / 1024;
    int nb_node = (NNODE + 1023) / 1024;
    int nb_pod  = (NPOD  + 1023) / 1024;
    scan1<<<nb_svc,  1024>>>(p_deg + DEG_SVC_DST, NSVC,  p_off + OFF_SVC,  p_part + 0);
    scan1<<<nb_node, 1024>>>(p_deg + DEG_PN_DST,  NNODE, p_off + OFF_NODE, p_part + 128);
    scan1<<<nb_pod,  1024>>>(p_deg + DEG_NP_DST,  NPOD,  p_off + OFF_POD,  p_part + 256);
    scan2<<<1, 128>>>(p_part + 0,   nb_svc);
    scan2<<<1, 128>>>(p_part + 128, nb_node);
    scan2<<<1, 128>>>(p_part + 256, nb_pod);
    scan3<<<nb_svc,  1024>>>(p_off + OFF_SVC,  NSVC,  p_part + 0);
    scan3<<<nb_node, 1024>>>(p_off + OFF_NODE, NNODE, p_part + 128);
    scan3<<<nb_pod,  1024>>>(p_off + OFF_POD,  NPOD,  p_part + 256);

    fill_kernel<<<(E_svc + 255) / 256, 256>>>(svc_src, svc_dst, E_svc,
                                              p_off + OFF_SVC,  p_fill + OFF_SVC,  p_esvc);
    fill_kernel<<<(E_pn  + 255) / 256, 256>>>(pn_src,  pn_dst,  E_pn,
                                              p_off + OFF_NODE, p_fill + OFF_NODE, p_epn);
    fill_kernel<<<(E_np  + 255) / 256, 256>>>(np_src,  np_dst,  E_np,
                                              p_off + OFF_POD,  p_fill + OFF_POD,  p_enp);

    gather_kernel<<<(NSVC  + 7) / 8, 256>>>(x_svc,  p_esvc, p_off + OFF_SVC,
                                            p_deg + DEG_SVC_DST, p_nrm + DEG_SVC_SRC,
                                            p_nrm + DEG_SVC_DST, p_agg + AGG_SVC_OFF, NSVC);
    gather_kernel<<<(NNODE + 7) / 8, 256>>>(x_pod,  p_epn,  p_off + OFF_NODE,
                                            p_deg + DEG_PN_DST,  p_nrm + DEG_PN_SRC,
                                            p_nrm + DEG_PN_DST,  p_agg + AGG_NODE_OFF, NNODE);
    gather_kernel<<<(NPOD  + 7) / 8, 256>>>(x_node, p_enp,  p_off + OFF_POD,
                                            p_deg + DEG_NP_DST,  p_nrm + DEG_NP_SRC,
                                            p_nrm + DEG_NP_DST,  p_agg + AGG_POD_OFF, NPOD);

    gemm_tc<<<(NSVC + 127) / 128, 256, SM_TOTAL>>>(
        p_agg + AGG_SVC_OFF, p_w1hi + 0 * 16384, p_w1lo + 0 * 16384,
        p_w2hi + 0 * 8192, p_w2lo + 0 * 8192, b_call, b_lin_svc, out, NSVC);
    gemm_tc<<<(NNODE + 127) / 128, 256, SM_TOTAL>>>(
        p_agg + AGG_NODE_OFF, p_w1hi + 1 * 16384, p_w1lo + 1 * 16384,
        p_w2hi + 1 * 8192, p_w2lo + 1 * 8192, b_in, b_lin_node,
        out + (size_t)NSVC * OUTD, NNODE);
    gemm_tc<<<(NPOD + 127) / 128, 256, SM_TOTAL>>>(
        p_agg + AGG_POD_OFF, p_w1hi + 2 * 16384, p_w1lo + 2 * 16384,
        p_w2hi + 2 * 8192, p_w2lo + 2 * 8192, b_ni, b_lin_pod,
        out + (size_t)(NSVC + NNODE) * OUTD, NPOD);
}

// round 5
// speedup vs baseline: 4.3189x; 1.5813x over previous
#include <cuda_runtime.h>
#include <cuda_bf16.h>
#include <cstdint>

#define NSVC 50000
#define NNODE 20000
#define NPOD 100000
#define FD 128
#define OUTD 64
#define ESVC_MAX 1600000
#define EPN_MAX  100000
#define ENP_MAX  100000

// ---- degree/norm array layout ----
#define DEG_SVC_SRC 0
#define DEG_SVC_DST (NSVC)
#define DEG_PN_SRC  (2*NSVC)
#define DEG_PN_DST  (2*NSVC + NPOD)
#define DEG_NP_SRC  (2*NSVC + NPOD + NNODE)
#define DEG_NP_DST  (2*NSVC + NPOD + 2*NNODE)
#define DEG_TOTAL   (2*NSVC + 2*NPOD + 2*NNODE)

#define OFF_SVC  0
#define OFF_NODE (NSVC)
#define OFF_POD  (NSVC + NNODE)
#define OFF_TOTAL (NSVC + NNODE + NPOD)

#define AGG_SVC_OFF  ((size_t)0)
#define AGG_NODE_OFF ((size_t)NSVC * FD)
#define AGG_POD_OFF  ((size_t)(NSVC + NNODE) * FD)
#define AGG_TOTAL    ((size_t)(NSVC + NNODE + NPOD) * FD)

__device__ float g_agg[AGG_TOTAL];
__device__ int   g_deg[DEG_TOTAL];
__device__ float g_nrm[DEG_TOTAL];
__device__ int   g_off[OFF_TOTAL];
__device__ int   g_fill[OFF_TOTAL];
__device__ int   g_part[3 * 128];
__device__ int   g_eidx_svc[ESVC_MAX];
__device__ int   g_eidx_pn[EPN_MAX];
__device__ int   g_eidx_np[ENP_MAX];

// pre-split transposed weights, plain [n][k] row-major bf16, per type
__device__ __nv_bfloat16 g_w1hi[3][128 * 128];
__device__ __nv_bfloat16 g_w1lo[3][128 * 128];
__device__ __nv_bfloat16 g_w2hi[3][64 * 128];
__device__ __nv_bfloat16 g_w2lo[3][64 * 128];

// ============================================================
// prep kernels
// ============================================================
__global__ void zero_kernel() {
    int stride = gridDim.x * blockDim.x;
    for (int i = blockIdx.x * blockDim.x + threadIdx.x; i < DEG_TOTAL; i += stride)
        g_deg[i] = 0;
    for (int i = blockIdx.x * blockDim.x + threadIdx.x; i < OFF_TOTAL; i += stride)
        g_fill[i] = 0;
}

__global__ void deg_kernel(const int* __restrict__ src, const int* __restrict__ dst,
                           int E, int off_s, int off_d) {
    int i = blockIdx.x * blockDim.x + threadIdx.x;
    if (i < E) {
        atomicAdd(&g_deg[off_s + src[i]], 1);
        atomicAdd(&g_deg[off_d + dst[i]], 1);
    }
}

__global__ void nrm_kernel() {
    int i = blockIdx.x * blockDim.x + threadIdx.x;
    if (i < DEG_TOTAL) {
        int d = g_deg[i];
        g_nrm[i] = rsqrtf((float)(d > 1 ? d : 1));
    }
}

__global__ void scan1(const int* __restrict__ deg, int n,
                      int* __restrict__ out, int* __restrict__ part) {
    __shared__ int s[1024];
    int t = threadIdx.x;
    int i = blockIdx.x * 1024 + t;
    int v = (i < n) ? deg[i] : 0;
    s[t] = v;
    __syncthreads();
    #pragma unroll
    for (int d = 1; d < 1024; d <<= 1) {
        int tv = (t >= d) ? s[t - d] : 0;
        __syncthreads();
        s[t] += tv;
        __syncthreads();
    }
    if (i < n) out[i] = s[t] - v;
    if (t == 1023) part[blockIdx.x] = s[t];
}

__global__ void scan2(int* part, int np) {
    __shared__ int s[128];
    int t = threadIdx.x;
    int v = (t < np) ? part[t] : 0;
    s[t] = v;
    __syncthreads();
    #pragma unroll
    for (int d = 1; d < 128; d <<= 1) {
        int tv = (t >= d) ? s[t - d] : 0;
        __syncthreads();
        s[t] += tv;
        __syncthreads();
    }
    if (t < np) part[t] = s[t] - v;
}

__global__ void scan3(int* __restrict__ out, int n, const int* __restrict__ part) {
    int i = blockIdx.x * 1024 + threadIdx.x;
    if (i < n) out[i] += part[blockIdx.x];
}

__global__ void fill_kernel(const int* __restrict__ src, const int* __restrict__ dst,
                            int E, const int* __restrict__ off,
                            int* __restrict__ fillc, int* __restrict__ eidx) {
    int i = blockIdx.x * blockDim.x + threadIdx.x;
    if (i < E) {
        int d = dst[i];
        int p = atomicAdd(&fillc[d], 1);
        eidx[off[d] + p] = src[i];
    }
}

__global__ void gather_kernel(const float* __restrict__ x,
                              const int* __restrict__ eidx,
                              const int* __restrict__ off,
                              const int* __restrict__ cnt,
                              const float* __restrict__ nsrc,
                              const float* __restrict__ ndst,
                              float* __restrict__ agg, int M) {
    int w = (blockIdx.x * blockDim.x + threadIdx.x) >> 5;
    int lane = threadIdx.x & 31;
    if (w >= M) return;
    int beg = off[w];
    int end = beg + cnt[w];
    const float4* x4 = reinterpret_cast<const float4*>(x);

    float4 acc = make_float4(0.f, 0.f, 0.f, 0.f);
    int e = beg;
    for (; e + 4 <= end; e += 4) {
        int s0 = __ldg(eidx + e + 0);
        int s1 = __ldg(eidx + e + 1);
        int s2 = __ldg(eidx + e + 2);
        int s3 = __ldg(eidx + e + 3);
        float n0 = __ldg(nsrc + s0);
        float n1 = __ldg(nsrc + s1);
        float n2 = __ldg(nsrc + s2);
        float n3 = __ldg(nsrc + s3);
        float4 v0 = x4[(size_t)s0 * 32 + lane];
        float4 v1 = x4[(size_t)s1 * 32 + lane];
        float4 v2 = x4[(size_t)s2 * 32 + lane];
        float4 v3 = x4[(size_t)s3 * 32 + lane];
        acc.x += v0.x * n0; acc.y += v0.y * n0; acc.z += v0.z * n0; acc.w += v0.w * n0;
        acc.x += v1.x * n1; acc.y += v1.y * n1; acc.z += v1.z * n1; acc.w += v1.w * n1;
        acc.x += v2.x * n2; acc.y += v2.y * n2; acc.z += v2.z * n2; acc.w += v2.w * n2;
        acc.x += v3.x * n3; acc.y += v3.y * n3; acc.z += v3.z * n3; acc.w += v3.w * n3;
    }
    for (; e < end; e++) {
        int s0 = __ldg(eidx + e);
        float n0 = __ldg(nsrc + s0);
        float4 v0 = x4[(size_t)s0 * 32 + lane];
        acc.x += v0.x * n0; acc.y += v0.y * n0; acc.z += v0.z * n0; acc.w += v0.w * n0;
    }
    float nd = ndst[w];
    reinterpret_cast<float4*>(agg)[(size_t)w * 32 + lane] =
        make_float4(acc.x * nd, acc.y * nd, acc.z * nd, acc.w * nd);
}

// ============================================================
// Weight conversion — fully element-parallel, one launch for all
// three types. Thread handles one (n,k) element: coalesced writes
// over k; reads strided but L2-resident (only 192KB total).
// layout per type t:
//   W1 fp32 [k(128)][n(128)] -> w1hi/w1lo [n][k]
//   W2 fp32 [k(128)][n(64)]  -> w2hi/w2lo [n][k]
// ============================================================
__global__ void convw_all(const float* __restrict__ W1_0, const float* __restrict__ W2_0,
                          const float* __restrict__ W1_1, const float* __restrict__ W2_1,
                          const float* __restrict__ W1_2, const float* __restrict__ W2_2) {
    int idx = blockIdx.x * blockDim.x + threadIdx.x;
    // 3 types x (16384 W1 + 8192 W2) = 73728 elements
    int t = idx / 24576;
    int r = idx % 24576;
    if (t >= 3) return;
    const float* W1 = (t == 0) ? W1_0 : (t == 1) ? W1_1 : W1_2;
    const float* W2 = (t == 0) ? W2_0 : (t == 1) ? W2_1 : W2_2;
    if (r < 16384) {
        int n = r >> 7, k = r & 127;
        float v = __ldg(W1 + k * 128 + n);
        __nv_bfloat16 hi = __float2bfloat16(v);
        __nv_bfloat16 lo = __float2bfloat16(v - __bfloat162float(hi));
        g_w1hi[t][n * 128 + k] = hi;
        g_w1lo[t][n * 128 + k] = lo;
    } else {
        int q = r - 16384;
        int n = q >> 7, k = q & 127;
        float v = __ldg(W2 + k * 64 + n);
        __nv_bfloat16 hi = __float2bfloat16(v);
        __nv_bfloat16 lo = __float2bfloat16(v - __bfloat162float(hi));
        g_w2hi[t][n * 128 + k] = hi;
        g_w2lo[t][n * 128 + k] = lo;
    }
}

// ============================================================
// mma.sync bf16 fused GEMM kernel (unchanged from R4 — it passed)
// ============================================================
#define SROW 136
#define SROWB 272
#define SM_A_HI 0
#define SM_A_LO 34816
#define SM_W1HI 69632
#define SM_W1LO 104448
#define SM_W2HI 139264
#define SM_W2LO 156672
#define SM_B1   174080
#define SM_B2   174592
#define SM_TOTAL 174848

__device__ __forceinline__ uint32_t pack_bf2(__nv_bfloat16 a, __nv_bfloat16 b) {
    return (uint32_t)__bfloat16_as_ushort(a) | ((uint32_t)__bfloat16_as_ushort(b) << 16);
}
__device__ __forceinline__ void split_bf(float v, __nv_bfloat16& hi, __nv_bfloat16& lo) {
    hi = __float2bfloat16(v);
    lo = __float2bfloat16(v - __bfloat162float(hi));
}
__device__ __forceinline__ void mma_bf16(float* c, uint32_t a0, uint32_t a1,
                                         uint32_t a2, uint32_t a3,
                                         uint32_t b0, uint32_t b1) {
    asm volatile(
        "mma.sync.aligned.m16n8k16.row.col.f32.bf16.bf16.f32 "
        "{%0,%1,%2,%3}, {%4,%5,%6,%7}, {%8,%9}, {%0,%1,%2,%3};"
        : "+f"(c[0]), "+f"(c[1]), "+f"(c[2]), "+f"(c[3])
        : "r"(a0), "r"(a1), "r"(a2), "r"(a3), "r"(b0), "r"(b1));
}
__device__ __forceinline__ uint32_t lds_u32(const char* base, int row, int col) {
    return *(const uint32_t*)(base + row * SROWB + col * 2);
}

__global__ void __launch_bounds__(256, 1)
gemm_tc(const float* __restrict__ agg,
        const __nv_bfloat16* __restrict__ w1hi, const __nv_bfloat16* __restrict__ w1lo,
        const __nv_bfloat16* __restrict__ w2hi, const __nv_bfloat16* __restrict__ w2lo,
        const float* __restrict__ b1, const float* __restrict__ b2,
        float* __restrict__ out, int M) {
    extern __shared__ char sm[];
    int tid = threadIdx.x;
    int wid = tid >> 5;
    int lane = tid & 31;
    int g = lane >> 2;
    int tig = lane & 3;

    // ---- stage weights into padded smem ----
    {
        const uint4* s1h = (const uint4*)w1hi;
        const uint4* s1l = (const uint4*)w1lo;
        #pragma unroll
        for (int i = 0; i < 8; i++) {
            int idx = i * 256 + tid;
            int row = idx >> 4, gq = idx & 15;
            *(uint4*)(sm + SM_W1HI + row * SROWB + gq * 16) = s1h[idx];
            *(uint4*)(sm + SM_W1LO + row * SROWB + gq * 16) = s1l[idx];
        }
        const uint4* s2h = (const uint4*)w2hi;
        const uint4* s2l = (const uint4*)w2lo;
        #pragma unroll
        for (int i = 0; i < 4; i++) {
            int idx = i * 256 + tid;
            int row = idx >> 4, gq = idx & 15;
            *(uint4*)(sm + SM_W2HI + row * SROWB + gq * 16) = s2h[idx];
            *(uint4*)(sm + SM_W2LO + row * SROWB + gq * 16) = s2l[idx];
        }
    }
    if (tid < 128) ((float*)(sm + SM_B1))[tid] = b1[tid];
    else if (tid < 192) ((float*)(sm + SM_B2))[tid - 128] = b2[tid - 128];

    // ---- load + split A tile ----
    {
        int row = tid >> 1;
        int half = (tid & 1) * 64;
        int grow = blockIdx.x * 128 + row;
        const float4* av = (const float4*)agg + (size_t)grow * 32 + (half >> 2);
        #pragma unroll
        for (int j = 0; j < 16; j++) {
            float4 v = (grow < M) ? av[j] : make_float4(0.f, 0.f, 0.f, 0.f);
            __nv_bfloat16 h0, h1, h2, h3, l0, l1, l2, l3;
            split_bf(v.x, h0, l0); split_bf(v.y, h1, l1);
            split_bf(v.z, h2, l2); split_bf(v.w, h3, l3);
            int col = half + j * 4;
            *(uint2*)(sm + SM_A_HI + row * SROWB + col * 2) =
                make_uint2(pack_bf2(h0, h1), pack_bf2(h2, h3));
            *(uint2*)(sm + SM_A_LO + row * SROWB + col * 2) =
                make_uint2(pack_bf2(l0, l1), pack_bf2(l2, l3));
        }
    }
    __syncthreads();

    int mtb = (wid & 3) * 2;
    int nb1 = (wid >> 2) * 64;

    // ---- GEMM1 ----
    float acc[2][8][4];
    #pragma unroll
    for (int mt = 0; mt < 2; mt++)
        #pragma unroll
        for (int nt = 0; nt < 8; nt++)
            #pragma unroll
            for (int q = 0; q < 4; q++) acc[mt][nt][q] = 0.f;

    #pragma unroll
    for (int kc = 0; kc < 8; kc++) {
        int k0 = kc * 16 + tig * 2;
        uint32_t ah[2][4], al[2][4];
        #pragma unroll
        for (int mt = 0; mt < 2; mt++) {
            int r = (mtb + mt) * 16 + g;
            ah[mt][0] = lds_u32(sm + SM_A_HI, r,     k0);
            ah[mt][1] = lds_u32(sm + SM_A_HI, r + 8, k0);
            ah[mt][2] = lds_u32(sm + SM_A_HI, r,     k0 + 8);
            ah[mt][3] = lds_u32(sm + SM_A_HI, r + 8, k0 + 8);
            al[mt][0] = lds_u32(sm + SM_A_LO, r,     k0);
            al[mt][1] = lds_u32(sm + SM_A_LO, r + 8, k0);
            al[mt][2] = lds_u32(sm + SM_A_LO, r,     k0 + 8);
            al[mt][3] = lds_u32(sm + SM_A_LO, r + 8, k0 + 8);
        }
        #pragma unroll
        for (int nt = 0; nt < 8; nt++) {
            int n = nb1 + nt * 8 + g;
            uint32_t bh0 = lds_u32(sm + SM_W1HI, n, k0);
            uint32_t bh1 = lds_u32(sm + SM_W1HI, n, k0 + 8);
            uint32_t bl0 = lds_u32(sm + SM_W1LO, n, k0);
            uint32_t bl1 = lds_u32(sm + SM_W1LO, n, k0 + 8);
            #pragma unroll
            for (int mt = 0; mt < 2; mt++) {
                mma_bf16(acc[mt][nt], ah[mt][0], ah[mt][1], ah[mt][2], ah[mt][3], bh0, bh1);
                mma_bf16(acc[mt][nt], al[mt][0], al[mt][1], al[mt][2], al[mt][3], bh0, bh1);
                mma_bf16(acc[mt][nt], ah[mt][0], ah[mt][1], ah[mt][2], ah[mt][3], bl0, bl1);
            }
        }
    }
    __syncthreads();

    // ---- epilogue1 ----
    {
        const float* b1s = (const float*)(sm + SM_B1);
        #pragma unroll
        for (int mt = 0; mt < 2; mt++) {
            #pragma unroll
            for (int nt = 0; nt < 8; nt++) {
                int row = (mtb + mt) * 16 + g;
                int col = nb1 + nt * 8 + tig * 2;
                float bb0 = b1s[col], bb1 = b1s[col + 1];
                float v0 = acc[mt][nt][0] + bb0;
                float v1 = acc[mt][nt][1] + bb1;
                float v2 = acc[mt][nt][2] + bb0;
                float v3 = acc[mt][nt][3] + bb1;
                v0 = v0 > 0.f ? v0 : 0.01f * v0;
                v1 = v1 > 0.f ? v1 : 0.01f * v1;
                v2 = v2 > 0.f ? v2 : 0.01f * v2;
                v3 = v3 > 0.f ? v3 : 0.01f * v3;
                __nv_bfloat16 h0, h1, h2, h3, l0, l1, l2, l3;
                split_bf(v0, h0, l0); split_bf(v1, h1, l1);
                split_bf(v2, h2, l2); split_bf(v3, h3, l3);
                *(uint32_t*)(sm + SM_A_HI + row * SROWB + col * 2) = pack_bf2(h0, h1);
                *(uint32_t*)(sm + SM_A_LO + row * SROWB + col * 2) = pack_bf2(l0, l1);
                *(uint32_t*)(sm + SM_A_HI + (row + 8) * SROWB + col * 2) = pack_bf2(h2, h3);
                *(uint32_t*)(sm + SM_A_LO + (row + 8) * SROWB + col * 2) = pack_bf2(l2, l3);
            }
        }
    }
    __syncthreads();

    // ---- GEMM2 ----
    int nb2 = (wid >> 2) * 32;
    float acc2[2][4][4];
    #pragma unroll
    for (int mt = 0; mt < 2; mt++)
        #pragma unroll
        for (int nt = 0; nt < 4; nt++)
            #pragma unroll
            for (int q = 0; q < 4; q++) acc2[mt][nt][q] = 0.f;

    #pragma unroll
    for (int kc = 0; kc < 8; kc++) {
        int k0 = kc * 16 + tig * 2;
        uint32_t ah[2][4], al[2][4];
        #pragma unroll
        for (int mt = 0; mt < 2; mt++) {
            int r = (mtb + mt) * 16 + g;
            ah[mt][0] = lds_u32(sm + SM_A_HI, r,     k0);
            ah[mt][1] = lds_u32(sm + SM_A_HI, r + 8, k0);
            ah[mt][2] = lds_u32(sm + SM_A_HI, r,     k0 + 8);
            ah[mt][3] = lds_u32(sm + SM_A_HI, r + 8, k0 + 8);
            al[mt][0] = lds_u32(sm + SM_A_LO, r,     k0);
            al[mt][1] = lds_u32(sm + SM_A_LO, r + 8, k0);
            al[mt][2] = lds_u32(sm + SM_A_LO, r,     k0 + 8);
            al[mt][3] = lds_u32(sm + SM_A_LO, r + 8, k0 + 8);
        }
        #pragma unroll
        for (int nt = 0; nt < 4; nt++) {
            int n = nb2 + nt * 8 + g;
            uint32_t bh0 = lds_u32(sm + SM_W2HI, n, k0);
            uint32_t bh1 = lds_u32(sm + SM_W2HI, n, k0 + 8);
            uint32_t bl0 = lds_u32(sm + SM_W2LO, n, k0);
            uint32_t bl1 = lds_u32(sm + SM_W2LO, n, k0 + 8);
            #pragma unroll
            for (int mt = 0; mt < 2; mt++) {
                mma_bf16(acc2[mt][nt], ah[mt][0], ah[mt][1], ah[mt][2], ah[mt][3], bh0, bh1);
                mma_bf16(acc2[mt][nt], al[mt][0], al[mt][1], al[mt][2], al[mt][3], bh0, bh1);
                mma_bf16(acc2[mt][nt], ah[mt][0], ah[mt][1], ah[mt][2], ah[mt][3], bl0, bl1);
            }
        }
    }

    // ---- epilogue2 ----
    {
        const float* b2s = (const float*)(sm + SM_B2);
        #pragma unroll
        for (int mt = 0; mt < 2; mt++) {
            #pragma unroll
            for (int nt = 0; nt < 4; nt++) {
                int row = blockIdx.x * 128 + (mtb + mt) * 16 + g;
                int col = nb2 + nt * 8 + tig * 2;
                float bb0 = b2s[col], bb1 = b2s[col + 1];
                if (row < M)
                    *(float2*)(out + (size_t)row * 64 + col) =
                        make_float2(acc2[mt][nt][0] + bb0, acc2[mt][nt][1] + bb1);
                if (row + 8 < M)
                    *(float2*)(out + (size_t)(row + 8) * 64 + col) =
                        make_float2(acc2[mt][nt][2] + bb0, acc2[mt][nt][3] + bb1);
            }
        }
    }
}

// ============================================================
// launch
// ============================================================
extern "C" void kernel_launch(void* const* d_in, const int* in_sizes, int n_in,
                              void* d_out, int out_size) {
    const float* x_svc  = (const float*)d_in[0];
    const float* x_pod  = (const float*)d_in[1];
    const float* x_node = (const float*)d_in[2];
    const int* svc_src = (const int*)d_in[3];
    const int* svc_dst = (const int*)d_in[4];
    const int* pn_src  = (const int*)d_in[5];
    const int* pn_dst  = (const int*)d_in[6];
    const int* np_src  = (const int*)d_in[7];
    const int* np_dst  = (const int*)d_in[8];
    const float* W_call = (const float*)d_in[9];
    const float* b_call = (const float*)d_in[10];
    const float* W_in   = (const float*)d_in[11];
    const float* b_in   = (const float*)d_in[12];
    const float* W_ni   = (const float*)d_in[13];
    const float* b_ni   = (const float*)d_in[14];
    const float* W_lin_svc  = (const float*)d_in[15];
    const float* b_lin_svc  = (const float*)d_in[16];
    const float* W_lin_node = (const float*)d_in[17];
    const float* b_lin_node = (const float*)d_in[18];
    const float* W_lin_pod  = (const float*)d_in[19];
    const float* b_lin_pod  = (const float*)d_in[20];
    float* out = (float*)d_out;

    int E_svc = in_sizes[3];
    int E_pn  = in_sizes[5];
    int E_np  = in_sizes[7];

    int *p_deg, *p_off, *p_fill, *p_part, *p_esvc, *p_epn, *p_enp;
    float *p_nrm, *p_agg;
    __nv_bfloat16 *p_w1hi, *p_w1lo, *p_w2hi, *p_w2lo;
    cudaGetSymbolAddress((void**)&p_deg,  g_deg);
    cudaGetSymbolAddress((void**)&p_off,  g_off);
    cudaGetSymbolAddress((void**)&p_fill, g_fill);
    cudaGetSymbolAddress((void**)&p_part, g_part);
    cudaGetSymbolAddress((void**)&p_esvc, g_eidx_svc);
    cudaGetSymbolAddress((void**)&p_epn,  g_eidx_pn);
    cudaGetSymbolAddress((void**)&p_enp,  g_eidx_np);
    cudaGetSymbolAddress((void**)&p_nrm,  g_nrm);
    cudaGetSymbolAddress((void**)&p_agg,  g_agg);
    cudaGetSymbolAddress((void**)&p_w1hi, g_w1hi);
    cudaGetSymbolAddress((void**)&p_w1lo, g_w1lo);
    cudaGetSymbolAddress((void**)&p_w2hi, g_w2hi);
    cudaGetSymbolAddress((void**)&p_w2lo, g_w2lo);

    cudaFuncSetAttribute(gemm_tc, cudaFuncAttributeMaxDynamicSharedMemorySize, SM_TOTAL);

    zero_kernel<<<256, 256>>>();

    // one fully-parallel weight conversion launch (73728 threads)
    convw_all<<<(73728 + 255) / 256, 256>>>(W_call, W_lin_svc, W_in, W_lin_node, W_ni, W_lin_pod);

    deg_kernel<<<(E_svc + 255) / 256, 256>>>(svc_src, svc_dst, E_svc, DEG_SVC_SRC, DEG_SVC_DST);
    deg_kernel<<<(E_pn  + 255) / 256, 256>>>(pn_src,  pn_dst,  E_pn,  DEG_PN_SRC,  DEG_PN_DST);
    deg_kernel<<<(E_np  + 255) / 256, 256>>>(np_src,  np_dst,  E_np,  DEG_NP_SRC,  DEG_NP_DST);

    nrm_kernel<<<(DEG_TOTAL + 255) / 256, 256>>>();

    int nb_svc  = (NSVC  + 1023) / 1024;
    int nb_node = (NNODE + 1023) / 1024;
    int nb_pod  = (NPOD  + 1023) / 1024;
    scan1<<<nb_svc,  1024>>>(p_deg + DEG_SVC_DST, NSVC,  p_off + OFF_SVC,  p_part + 0);
    scan1<<<nb_node, 1024>>>(p_deg + DEG_PN_DST,  NNODE, p_off + OFF_NODE, p_part + 128);
    scan1<<<nb_pod,  1024>>>(p_deg + DEG_NP_DST,  NPOD,  p_off + OFF_POD,  p_part + 256);
    scan2<<<1, 128>>>(p_part + 0,   nb_svc);
    scan2<<<1, 128>>>(p_part + 128, nb_node);
    scan2<<<1, 128>>>(p_part + 256, nb_pod);
    scan3<<<nb_svc,  1024>>>(p_off + OFF_SVC,  NSVC,  p_part + 0);
    scan3<<<nb_node, 1024>>>(p_off + OFF_NODE, NNODE, p_part + 128);
    scan3<<<nb_pod,  1024>>>(p_off + OFF_POD,  NPOD,  p_part + 256);

    fill_kernel<<<(E_svc + 255) / 256, 256>>>(svc_src, svc_dst, E_svc,
                                              p_off + OFF_SVC,  p_fill + OFF_SVC,  p_esvc);
    fill_kernel<<<(E_pn  + 255) / 256, 256>>>(pn_src,  pn_dst,  E_pn,
                                              p_off + OFF_NODE, p_fill + OFF_NODE, p_epn);
    fill_kernel<<<(E_np  + 255) / 256, 256>>>(np_src,  np_dst,  E_np,
                                              p_off + OFF_POD,  p_fill + OFF_POD,  p_enp);

    gather_kernel<<<(NSVC  + 7) / 8, 256>>>(x_svc,  p_esvc, p_off + OFF_SVC,
                                            p_deg + DEG_SVC_DST, p_nrm + DEG_SVC_SRC,
                                            p_nrm + DEG_SVC_DST, p_agg + AGG_SVC_OFF, NSVC);
    gather_kernel<<<(NNODE + 7) / 8, 256>>>(x_pod,  p_epn,  p_off + OFF_NODE,
                                            p_deg + DEG_PN_DST,  p_nrm + DEG_PN_SRC,
                                            p_nrm + DEG_PN_DST,  p_agg + AGG_NODE_OFF, NNODE);
    gather_kernel<<<(NPOD  + 7) / 8, 256>>>(x_node, p_enp,  p_off + OFF_POD,
                                            p_deg + DEG_NP_DST,  p_nrm + DEG_NP_SRC,
                                            p_nrm + DEG_NP_DST,  p_agg + AGG_POD_OFF, NPOD);

    gemm_tc<<<(NSVC + 127) / 128, 256, SM_TOTAL>>>(
        p_agg + AGG_SVC_OFF, p_w1hi + 0 * 16384, p_w1lo + 0 * 16384,
        p_w2hi + 0 * 8192, p_w2lo + 0 * 8192, b_call, b_lin_svc, out, NSVC);
    gemm_tc<<<(NNODE + 127) / 128, 256, SM_TOTAL>>>(
        p_agg + AGG_NODE_OFF, p_w1hi + 1 * 16384, p_w1lo + 1 * 16384,
        p_w2hi + 1 * 8192, p_w2lo + 1 * 8192, b_in, b_lin_node,
        out + (size_t)NSVC * OUTD, NNODE);
    gemm_tc<<<(NPOD + 127) / 128, 256, SM_TOTAL>>>(
        p_agg + AGG_POD_OFF, p_w1hi + 2 * 16384, p_w1lo + 2 * 16384,
        p_w2hi + 2 * 8192, p_w2lo + 2 * 8192, b_ni, b_lin_pod,
        out + (size_t)(NSVC + NNODE) * OUTD, NPOD);
}

// round 9
// speedup vs baseline: 5.0255x; 1.1636x over previous
#include <cuda_runtime.h>
#include <cuda_bf16.h>
#include <cstdint>

#define NSVC 50000
#define NNODE 20000
#define NPOD 100000
#define FD 128
#define OUTD 64
#define ESVC_MAX 1600000
#define EPN_MAX  100000
#define ENP_MAX  100000

// ---- degree/norm array layout ----
#define DEG_SVC_SRC 0
#define DEG_SVC_DST (NSVC)
#define DEG_PN_SRC  (2*NSVC)
#define DEG_PN_DST  (2*NSVC + NPOD)
#define DEG_NP_SRC  (2*NSVC + NPOD + NNODE)
#define DEG_NP_DST  (2*NSVC + NPOD + 2*NNODE)
#define DEG_TOTAL   (2*NSVC + 2*NPOD + 2*NNODE)

#define OFF_SVC  0
#define OFF_NODE (NSVC)
#define OFF_POD  (NSVC + NNODE)
#define OFF_TOTAL (NSVC + NNODE + NPOD)

#define AGG_SVC_OFF  ((size_t)0)
#define AGG_NODE_OFF ((size_t)NSVC * FD)
#define AGG_POD_OFF  ((size_t)(NSVC + NNODE) * FD)
#define AGG_TOTAL    ((size_t)(NSVC + NNODE + NPOD) * FD)

// scan block mapping (1024-wide blocks)
#define NB_SVC  49   /* ceil(50000/1024)  */
#define NB_NODE 20   /* ceil(20000/1024)  */
#define NB_POD  98   /* ceil(100000/1024) */
#define NB_ALL  167

// gemm block mapping (128 rows/block)
#define GB_SVC  391
#define GB_NODE 157
#define GB_POD  782
#define GB_ALL  1330

__device__ float g_agg[AGG_TOTAL];
__device__ int   g_deg[DEG_TOTAL];
__device__ float g_nrm[DEG_TOTAL];
__device__ int   g_off[OFF_TOTAL];
__device__ int   g_fill[OFF_TOTAL];
__device__ int   g_part[3 * 128];
__device__ int   g_eidx_svc[ESVC_MAX];
__device__ int   g_eidx_pn[EPN_MAX];
__device__ int   g_eidx_np[ENP_MAX];

__device__ __nv_bfloat16 g_w1hi[3][128 * 128];
__device__ __nv_bfloat16 g_w1lo[3][128 * 128];
__device__ __nv_bfloat16 g_w2hi[3][64 * 128];
__device__ __nv_bfloat16 g_w2lo[3][64 * 128];

// ============================================================
// K1: zero counters + weight conversion (fused)
// ============================================================
__global__ void prep0(const float* __restrict__ W1_0, const float* __restrict__ W2_0,
                      const float* __restrict__ W1_1, const float* __restrict__ W2_1,
                      const float* __restrict__ W1_2, const float* __restrict__ W2_2) {
    int tid0 = blockIdx.x * blockDim.x + threadIdx.x;
    int stride = gridDim.x * blockDim.x;
    for (int i = tid0; i < DEG_TOTAL; i += stride) g_deg[i] = 0;
    for (int i = tid0; i < OFF_TOTAL; i += stride) g_fill[i] = 0;

    int idx = tid0;
    if (idx < 73728) {
        int t = idx / 24576;
        int r = idx % 24576;
        const float* W1 = (t == 0) ? W1_0 : (t == 1) ? W1_1 : W1_2;
        const float* W2 = (t == 0) ? W2_0 : (t == 1) ? W2_1 : W2_2;
        if (r < 16384) {
            int n = r >> 7, k = r & 127;
            float v = __ldg(W1 + k * 128 + n);
            __nv_bfloat16 hi = __float2bfloat16(v);
            __nv_bfloat16 lo = __float2bfloat16(v - __bfloat162float(hi));
            g_w1hi[t][n * 128 + k] = hi;
            g_w1lo[t][n * 128 + k] = lo;
        } else {
            int q = r - 16384;
            int n = q >> 7, k = q & 127;
            float v = __ldg(W2 + k * 64 + n);
            __nv_bfloat16 hi = __float2bfloat16(v);
            __nv_bfloat16 lo = __float2bfloat16(v - __bfloat162float(hi));
            g_w2hi[t][n * 128 + k] = hi;
            g_w2lo[t][n * 128 + k] = lo;
        }
    }
}

// ============================================================
// K2: degree counting, all three edge types in one grid
// ============================================================
__global__ void deg_all(const int* __restrict__ svc_src, const int* __restrict__ svc_dst,
                        const int* __restrict__ pn_src,  const int* __restrict__ pn_dst,
                        const int* __restrict__ np_src,  const int* __restrict__ np_dst,
                        int E_svc, int E_pn, int E_np) {
    int i = blockIdx.x * blockDim.x + threadIdx.x;
    if (i < E_svc) {
        atomicAdd(&g_deg[DEG_SVC_SRC + svc_src[i]], 1);
        atomicAdd(&g_deg[DEG_SVC_DST + svc_dst[i]], 1);
    } else if (i < E_svc + E_pn) {
        int e = i - E_svc;
        atomicAdd(&g_deg[DEG_PN_SRC + pn_src[e]], 1);
        atomicAdd(&g_deg[DEG_PN_DST + pn_dst[e]], 1);
    } else if (i < E_svc + E_pn + E_np) {
        int e = i - E_svc - E_pn;
        atomicAdd(&g_deg[DEG_NP_SRC + np_src[e]], 1);
        atomicAdd(&g_deg[DEG_NP_DST + np_dst[e]], 1);
    }
}

// ============================================================
// K3: combined per-type block scan (stage 1) + nrm computation
// ============================================================
__device__ __forceinline__ void scan_map(int b, int& t, int& lb,
                                         const int*& deg, int*& out, int& n) {
    if (b < NB_SVC)           { t = 0; lb = b;                     deg = g_deg + DEG_SVC_DST; out = g_off + OFF_SVC;  n = NSVC; }
    else if (b < NB_SVC+NB_NODE){ t = 1; lb = b - NB_SVC;          deg = g_deg + DEG_PN_DST;  out = g_off + OFF_NODE; n = NNODE; }
    else                      { t = 2; lb = b - NB_SVC - NB_NODE;  deg = g_deg + DEG_NP_DST;  out = g_off + OFF_POD;  n = NPOD; }
}

__global__ void scan1_all() {
    // fused nrm: grid-stride over all degrees
    {
        int tid0 = blockIdx.x * blockDim.x + threadIdx.x;
        int stride = gridDim.x * blockDim.x;
        for (int i = tid0; i < DEG_TOTAL; i += stride) {
            int d = g_deg[i];
            g_nrm[i] = rsqrtf((float)(d > 1 ? d : 1));
        }
    }
    __shared__ int s[1024];
    int t, lb, n;
    const int* deg;
    int* out;
    scan_map(blockIdx.x, t, lb, deg, out, n);
    int tt = threadIdx.x;
    int i = lb * 1024 + tt;
    int v = (i < n) ? deg[i] : 0;
    s[tt] = v;
    __syncthreads();
    #pragma unroll
    for (int d = 1; d < 1024; d <<= 1) {
        int tv = (tt >= d) ? s[tt - d] : 0;
        __syncthreads();
        s[tt] += tv;
        __syncthreads();
    }
    if (i < n) out[i] = s[tt] - v;
    if (tt == 1023) g_part[t * 128 + lb] = s[tt];
}

__global__ void scan2_all() {
    __shared__ int s[128];
    int t = blockIdx.x;
    int np = (t == 0) ? NB_SVC : (t == 1) ? NB_NODE : NB_POD;
    int tt = threadIdx.x;
    int v = (tt < np) ? g_part[t * 128 + tt] : 0;
    s[tt] = v;
    __syncthreads();
    #pragma unroll
    for (int d = 1; d < 128; d <<= 1) {
        int tv = (tt >= d) ? s[tt - d] : 0;
        __syncthreads();
        s[tt] += tv;
        __syncthreads();
    }
    if (tt < np) g_part[t * 128 + tt] = s[tt] - v;
}

__global__ void scan3_all() {
    int t, lb, n;
    const int* deg;
    int* out;
    scan_map(blockIdx.x, t, lb, deg, out, n);
    int i = lb * 1024 + threadIdx.x;
    if (i < n) out[i] += g_part[t * 128 + lb];
}

// ============================================================
// K4: fill CSR edge lists, all types
// ============================================================
__global__ void fill_all(const int* __restrict__ svc_src, const int* __restrict__ svc_dst,
                         const int* __restrict__ pn_src,  const int* __restrict__ pn_dst,
                         const int* __restrict__ np_src,  const int* __restrict__ np_dst,
                         int E_svc, int E_pn, int E_np) {
    int i = blockIdx.x * blockDim.x + threadIdx.x;
    if (i < E_svc) {
        int d = svc_dst[i];
        int p = atomicAdd(&g_fill[OFF_SVC + d], 1);
        g_eidx_svc[g_off[OFF_SVC + d] + p] = svc_src[i];
    } else if (i < E_svc + E_pn) {
        int e = i - E_svc;
        int d = pn_dst[e];
        int p = atomicAdd(&g_fill[OFF_NODE + d], 1);
        g_eidx_pn[g_off[OFF_NODE + d] + p] = pn_src[e];
    } else if (i < E_svc + E_pn + E_np) {
        int e = i - E_svc - E_pn;
        int d = np_dst[e];
        int p = atomicAdd(&g_fill[OFF_POD + d], 1);
        g_eidx_np[g_off[OFF_POD + d] + p] = np_src[e];
    }
}

// ============================================================
// K5: warp-per-dst-row gather, all types in one grid
// ============================================================
__global__ void gather_all(const float* __restrict__ x_svc,
                           const float* __restrict__ x_pod,
                           const float* __restrict__ x_node) {
    int w = (blockIdx.x * blockDim.x + threadIdx.x) >> 5;
    int lane = threadIdx.x & 31;
    if (w >= OFF_TOTAL) return;

    const float* x;
    const int* eidx;
    const int* off;
    const int* cnt;
    const float* nsrc;
    const float* ndst;
    float* agg;
    int local;
    if (w < NSVC) {
        local = w;
        x = x_svc; eidx = g_eidx_svc; off = g_off + OFF_SVC;
        cnt = g_deg + DEG_SVC_DST; nsrc = g_nrm + DEG_SVC_SRC; ndst = g_nrm + DEG_SVC_DST;
        agg = g_agg + AGG_SVC_OFF;
    } else if (w < NSVC + NNODE) {
        local = w - NSVC;
        x = x_pod; eidx = g_eidx_pn; off = g_off + OFF_NODE;
        cnt = g_deg + DEG_PN_DST; nsrc = g_nrm + DEG_PN_SRC; ndst = g_nrm + DEG_PN_DST;
        agg = g_agg + AGG_NODE_OFF;
    } else {
        local = w - NSVC - NNODE;
        x = x_node; eidx = g_eidx_np; off = g_off + OFF_POD;
        cnt = g_deg + DEG_NP_DST; nsrc = g_nrm + DEG_NP_SRC; ndst = g_nrm + DEG_NP_DST;
        agg = g_agg + AGG_POD_OFF;
    }

    int beg = off[local];
    int end = beg + cnt[local];
    const float4* x4 = reinterpret_cast<const float4*>(x);

    float4 acc = make_float4(0.f, 0.f, 0.f, 0.f);
    int e = beg;
    for (; e + 4 <= end; e += 4) {
        int s0 = __ldg(eidx + e + 0);
        int s1 = __ldg(eidx + e + 1);
        int s2 = __ldg(eidx + e + 2);
        int s3 = __ldg(eidx + e + 3);
        float n0 = __ldg(nsrc + s0);
        float n1 = __ldg(nsrc + s1);
        float n2 = __ldg(nsrc + s2);
        float n3 = __ldg(nsrc + s3);
        float4 v0 = x4[(size_t)s0 * 32 + lane];
        float4 v1 = x4[(size_t)s1 * 32 + lane];
        float4 v2 = x4[(size_t)s2 * 32 + lane];
        float4 v3 = x4[(size_t)s3 * 32 + lane];
        acc.x += v0.x * n0; acc.y += v0.y * n0; acc.z += v0.z * n0; acc.w += v0.w * n0;
        acc.x += v1.x * n1; acc.y += v1.y * n1; acc.z += v1.z * n1; acc.w += v1.w * n1;
        acc.x += v2.x * n2; acc.y += v2.y * n2; acc.z += v2.z * n2; acc.w += v2.w * n2;
        acc.x += v3.x * n3; acc.y += v3.y * n3; acc.z += v3.z * n3; acc.w += v3.w * n3;
    }
    for (; e < end; e++) {
        int s0 = __ldg(eidx + e);
        float n0 = __ldg(nsrc + s0);
        float4 v0 = x4[(size_t)s0 * 32 + lane];
        acc.x += v0.x * n0; acc.y += v0.y * n0; acc.z += v0.z * n0; acc.w += v0.w * n0;
    }
    float nd = ndst[local];
    reinterpret_cast<float4*>(agg)[(size_t)local * 32 + lane] =
        make_float4(acc.x * nd, acc.y * nd, acc.z * nd, acc.w * nd);
}

// ============================================================
// K6: fused mma.sync GEMM, all types in one grid
// ============================================================
#define SROWB 272
#define SM_A_HI 0
#define SM_A_LO 34816
#define SM_W1HI 69632
#define SM_W1LO 104448
#define SM_W2HI 139264
#define SM_W2LO 156672
#define SM_B1   174080
#define SM_B2   174592
#define SM_TOTAL 174848

__device__ __forceinline__ uint32_t pack_bf2(__nv_bfloat16 a, __nv_bfloat16 b) {
    return (uint32_t)__bfloat16_as_ushort(a) | ((uint32_t)__bfloat16_as_ushort(b) << 16);
}
__device__ __forceinline__ void split_bf(float v, __nv_bfloat16& hi, __nv_bfloat16& lo) {
    hi = __float2bfloat16(v);
    lo = __float2bfloat16(v - __bfloat162float(hi));
}
__device__ __forceinline__ void mma_bf16(float* c, uint32_t a0, uint32_t a1,
                                         uint32_t a2, uint32_t a3,
                                         uint32_t b0, uint32_t b1) {
    asm volatile(
        "mma.sync.aligned.m16n8k16.row.col.f32.bf16.bf16.f32 "
        "{%0,%1,%2,%3}, {%4,%5,%6,%7}, {%8,%9}, {%0,%1,%2,%3};"
        : "+f"(c[0]), "+f"(c[1]), "+f"(c[2]), "+f"(c[3])
        : "r"(a0), "r"(a1), "r"(a2), "r"(a3), "r"(b0), "r"(b1));
}
__device__ __forceinline__ uint32_t lds_u32(const char* base, int row, int col) {
    return *(const uint32_t*)(base + row * SROWB + col * 2);
}

__global__ void __launch_bounds__(256, 1)
gemm_all(const float* __restrict__ b_call, const float* __restrict__ b_lin_svc,
         const float* __restrict__ b_in,   const float* __restrict__ b_lin_node,
         const float* __restrict__ b_ni,   const float* __restrict__ b_lin_pod,
         float* __restrict__ out_base) {
    extern __shared__ char sm[];
    int tid = threadIdx.x;
    int wid = tid >> 5;
    int lane = tid & 31;
    int g = lane >> 2;
    int tig = lane & 3;

    // block -> (type, local block)
    int b = blockIdx.x;
    int t, lb, M;
    const float* agg;
    const float* b1;
    const float* b2;
    float* out;
    if (b < GB_SVC) {
        t = 0; lb = b; M = NSVC;
        agg = g_agg + AGG_SVC_OFF; b1 = b_call; b2 = b_lin_svc;
        out = out_base;
    } else if (b < GB_SVC + GB_NODE) {
        t = 1; lb = b - GB_SVC; M = NNODE;
        agg = g_agg + AGG_NODE_OFF; b1 = b_in; b2 = b_lin_node;
        out = out_base + (size_t)NSVC * OUTD;
    } else {
        t = 2; lb = b - GB_SVC - GB_NODE; M = NPOD;
        agg = g_agg + AGG_POD_OFF; b1 = b_ni; b2 = b_lin_pod;
        out = out_base + (size_t)(NSVC + NNODE) * OUTD;
    }

    // ---- stage weights (device globals indexed by type) ----
    {
        const uint4* s1h = (const uint4*)g_w1hi[t];
        const uint4* s1l = (const uint4*)g_w1lo[t];
        #pragma unroll
        for (int i = 0; i < 8; i++) {
            int idx = i * 256 + tid;
            int row = idx >> 4, gq = idx & 15;
            *(uint4*)(sm + SM_W1HI + row * SROWB + gq * 16) = s1h[idx];
            *(uint4*)(sm + SM_W1LO + row * SROWB + gq * 16) = s1l[idx];
        }
        const uint4* s2h = (const uint4*)g_w2hi[t];
        const uint4* s2l = (const uint4*)g_w2lo[t];
        #pragma unroll
        for (int i = 0; i < 4; i++) {
            int idx = i * 256 + tid;
            int row = idx >> 4, gq = idx & 15;
            *(uint4*)(sm + SM_W2HI + row * SROWB + gq * 16) = s2h[idx];
            *(uint4*)(sm + SM_W2LO + row * SROWB + gq * 16) = s2l[idx];
        }
    }
    if (tid < 128) ((float*)(sm + SM_B1))[tid] = b1[tid];
    else if (tid < 192) ((float*)(sm + SM_B2))[tid - 128] = b2[tid - 128];

    // ---- load + split A tile ----
    {
        int row = tid >> 1;
        int half = (tid & 1) * 64;
        int grow = lb * 128 + row;
        const float4* av = (const float4*)agg + (size_t)grow * 32 + (half >> 2);
        #pragma unroll
        for (int j = 0; j < 16; j++) {
            float4 v = (grow < M) ? av[j] : make_float4(0.f, 0.f, 0.f, 0.f);
            __nv_bfloat16 h0, h1, h2, h3, l0, l1, l2, l3;
            split_bf(v.x, h0, l0); split_bf(v.y, h1, l1);
            split_bf(v.z, h2, l2); split_bf(v.w, h3, l3);
            int col = half + j * 4;
            *(uint2*)(sm + SM_A_HI + row * SROWB + col * 2) =
                make_uint2(pack_bf2(h0, h1), pack_bf2(h2, h3));
            *(uint2*)(sm + SM_A_LO + row * SROWB + col * 2) =
                make_uint2(pack_bf2(l0, l1), pack_bf2(l2, l3));
        }
    }
    __syncthreads();

    int mtb = (wid & 3) * 2;
    int nb1 = (wid >> 2) * 64;

    // ---- GEMM1 ----
    float acc[2][8][4];
    #pragma unroll
    for (int mt = 0; mt < 2; mt++)
        #pragma unroll
        for (int nt = 0; nt < 8; nt++)
            #pragma unroll
            for (int q = 0; q < 4; q++) acc[mt][nt][q] = 0.f;

    #pragma unroll
    for (int kc = 0; kc < 8; kc++) {
        int k0 = kc * 16 + tig * 2;
        uint32_t ah[2][4], al[2][4];
        #pragma unroll
        for (int mt = 0; mt < 2; mt++) {
            int r = (mtb + mt) * 16 + g;
            ah[mt][0] = lds_u32(sm + SM_A_HI, r,     k0);
            ah[mt][1] = lds_u32(sm + SM_A_HI, r + 8, k0);
            ah[mt][2] = lds_u32(sm + SM_A_HI, r,     k0 + 8);
            ah[mt][3] = lds_u32(sm + SM_A_HI, r + 8, k0 + 8);
            al[mt][0] = lds_u32(sm + SM_A_LO, r,     k0);
            al[mt][1] = lds_u32(sm + SM_A_LO, r + 8, k0);
            al[mt][2] = lds_u32(sm + SM_A_LO, r,     k0 + 8);
            al[mt][3] = lds_u32(sm + SM_A_LO, r + 8, k0 + 8);
        }
        #pragma unroll
        for (int nt = 0; nt < 8; nt++) {
            int n = nb1 + nt * 8 + g;
            uint32_t bh0 = lds_u32(sm + SM_W1HI, n, k0);
            uint32_t bh1 = lds_u32(sm + SM_W1HI, n, k0 + 8);
            uint32_t bl0 = lds_u32(sm + SM_W1LO, n, k0);
            uint32_t bl1 = lds_u32(sm + SM_W1LO, n, k0 + 8);
            #pragma unroll
            for (int mt = 0; mt < 2; mt++) {
                mma_bf16(acc[mt][nt], ah[mt][0], ah[mt][1], ah[mt][2], ah[mt][3], bh0, bh1);
                mma_bf16(acc[mt][nt], al[mt][0], al[mt][1], al[mt][2], al[mt][3], bh0, bh1);
                mma_bf16(acc[mt][nt], ah[mt][0], ah[mt][1], ah[mt][2], ah[mt][3], bl0, bl1);
            }
        }
    }
    __syncthreads();

    // ---- epilogue1 ----
    {
        const float* b1s = (const float*)(sm + SM_B1);
        #pragma unroll
        for (int mt = 0; mt < 2; mt++) {
            #pragma unroll
            for (int nt = 0; nt < 8; nt++) {
                int row = (mtb + mt) * 16 + g;
                int col = nb1 + nt * 8 + tig * 2;
                float bb0 = b1s[col], bb1 = b1s[col + 1];
                float v0 = acc[mt][nt][0] + bb0;
                float v1 = acc[mt][nt][1] + bb1;
                float v2 = acc[mt][nt][2] + bb0;
                float v3 = acc[mt][nt][3] + bb1;
                v0 = v0 > 0.f ? v0 : 0.01f * v0;
                v1 = v1 > 0.f ? v1 : 0.01f * v1;
                v2 = v2 > 0.f ? v2 : 0.01f * v2;
                v3 = v3 > 0.f ? v3 : 0.01f * v3;
                __nv_bfloat16 h0, h1, h2, h3, l0, l1, l2, l3;
                split_bf(v0, h0, l0); split_bf(v1, h1, l1);
                split_bf(v2, h2, l2); split_bf(v3, h3, l3);
                *(uint32_t*)(sm + SM_A_HI + row * SROWB + col * 2) = pack_bf2(h0, h1);
                *(uint32_t*)(sm + SM_A_LO + row * SROWB + col * 2) = pack_bf2(l0, l1);
                *(uint32_t*)(sm + SM_A_HI + (row + 8) * SROWB + col * 2) = pack_bf2(h2, h3);
                *(uint32_t*)(sm + SM_A_LO + (row + 8) * SROWB + col * 2) = pack_bf2(l2, l3);
            }
        }
    }
    __syncthreads();

    // ---- GEMM2 ----
    int nb2 = (wid >> 2) * 32;
    float acc2[2][4][4];
    #pragma unroll
    for (int mt = 0; mt < 2; mt++)
        #pragma unroll
        for (int nt = 0; nt < 4; nt++)
            #pragma unroll
            for (int q = 0; q < 4; q++) acc2[mt][nt][q] = 0.f;

    #pragma unroll
    for (int kc = 0; kc < 8; kc++) {
        int k0 = kc * 16 + tig * 2;
        uint32_t ah[2][4], al[2][4];
        #pragma unroll
        for (int mt = 0; mt < 2; mt++) {
            int r = (mtb + mt) * 16 + g;
            ah[mt][0] = lds_u32(sm + SM_A_HI, r,     k0);
            ah[mt][1] = lds_u32(sm + SM_A_HI, r + 8, k0);
            ah[mt][2] = lds_u32(sm + SM_A_HI, r,     k0 + 8);
            ah[mt][3] = lds_u32(sm + SM_A_HI, r + 8, k0 + 8);
            al[mt][0] = lds_u32(sm + SM_A_LO, r,     k0);
            al[mt][1] = lds_u32(sm + SM_A_LO, r + 8, k0);
            al[mt][2] = lds_u32(sm + SM_A_LO, r,     k0 + 8);
            al[mt][3] = lds_u32(sm + SM_A_LO, r + 8, k0 + 8);
        }
        #pragma unroll
        for (int nt = 0; nt < 4; nt++) {
            int n = nb2 + nt * 8 + g;
            uint32_t bh0 = lds_u32(sm + SM_W2HI, n, k0);
            uint32_t bh1 = lds_u32(sm + SM_W2HI, n, k0 + 8);
            uint32_t bl0 = lds_u32(sm + SM_W2LO, n, k0);
            uint32_t bl1 = lds_u32(sm + SM_W2LO, n, k0 + 8);
            #pragma unroll
            for (int mt = 0; mt < 2; mt++) {
                mma_bf16(acc2[mt][nt], ah[mt][0], ah[mt][1], ah[mt][2], ah[mt][3], bh0, bh1);
                mma_bf16(acc2[mt][nt], al[mt][0], al[mt][1], al[mt][2], al[mt][3], bh0, bh1);
                mma_bf16(acc2[mt][nt], ah[mt][0], ah[mt][1], ah[mt][2], ah[mt][3], bl0, bl1);
            }
        }
    }

    // ---- epilogue2 ----
    {
        const float* b2s = (const float*)(sm + SM_B2);
        #pragma unroll
        for (int mt = 0; mt < 2; mt++) {
            #pragma unroll
            for (int nt = 0; nt < 4; nt++) {
                int row = lb * 128 + (mtb + mt) * 16 + g;
                int col = nb2 + nt * 8 + tig * 2;
                float bb0 = b2s[col], bb1 = b2s[col + 1];
                if (row < M)
                    *(float2*)(out + (size_t)row * 64 + col) =
                        make_float2(acc2[mt][nt][0] + bb0, acc2[mt][nt][1] + bb1);
                if (row + 8 < M)
                    *(float2*)(out + (size_t)(row + 8) * 64 + col) =
                        make_float2(acc2[mt][nt][2] + bb0, acc2[mt][nt][3] + bb1);
            }
        }
    }
}

// ============================================================
// launch — 8 kernels total
// ============================================================
extern "C" void kernel_launch(void* const* d_in, const int* in_sizes, int n_in,
                              void* d_out, int out_size) {
    const float* x_svc  = (const float*)d_in[0];
    const float* x_pod  = (const float*)d_in[1];
    const float* x_node = (const float*)d_in[2];
    const int* svc_src = (const int*)d_in[3];
    const int* svc_dst = (const int*)d_in[4];
    const int* pn_src  = (const int*)d_in[5];
    const int* pn_dst  = (const int*)d_in[6];
    const int* np_src  = (const int*)d_in[7];
    const int* np_dst  = (const int*)d_in[8];
    const float* W_call = (const float*)d_in[9];
    const float* b_call = (const float*)d_in[10];
    const float* W_in   = (const float*)d_in[11];
    const float* b_in   = (const float*)d_in[12];
    const float* W_ni   = (const float*)d_in[13];
    const float* b_ni   = (const float*)d_in[14];
    const float* W_lin_svc  = (const float*)d_in[15];
    const float* b_lin_svc  = (const float*)d_in[16];
    const float* W_lin_node = (const float*)d_in[17];
    const float* b_lin_node = (const float*)d_in[18];
    const float* W_lin_pod  = (const float*)d_in[19];
    const float* b_lin_pod  = (const float*)d_in[20];
    float* out = (float*)d_out;

    int E_svc = in_sizes[3];
    int E_pn  = in_sizes[5];
    int E_np  = in_sizes[7];
    int E_tot = E_svc + E_pn + E_np;

    cudaFuncSetAttribute(gemm_all, cudaFuncAttributeMaxDynamicSharedMemorySize, SM_TOTAL);

    prep0<<<512, 256>>>(W_call, W_lin_svc, W_in, W_lin_node, W_ni, W_lin_pod);

    deg_all<<<(E_tot + 255) / 256, 256>>>(svc_src, svc_dst, pn_src, pn_dst,
                                          np_src, np_dst, E_svc, E_pn, E_np);

    scan1_all<<<NB_ALL, 1024>>>();
    scan2_all<<<3, 128>>>();
    scan3_all<<<NB_ALL, 1024>>>();

    fill_all<<<(E_tot + 255) / 256, 256>>>(svc_src, svc_dst, pn_src, pn_dst,
                                           np_src, np_dst, E_svc, E_pn, E_np);

    gather_all<<<(OFF_TOTAL + 7) / 8, 256>>>(x_svc, x_pod, x_node);

    gemm_all<<<GB_ALL, 256, SM_TOTAL>>>(b_call, b_lin_svc, b_in, b_lin_node,
                                        b_ni, b_lin_pod, out);
}

// round 10
// speedup vs baseline: 5.4457x; 1.0836x over previous
#include <cuda_runtime.h>
#include <cuda_fp16.h>
#include <cstdint>

#define NSVC 50000
#define NNODE 20000
#define NPOD 100000
#define FD 128
#define OUTD 64
#define ESVC_MAX 1600000
#define EPN_MAX  100000
#define ENP_MAX  100000

// ---- degree/norm array layout ----
#define DEG_SVC_SRC 0
#define DEG_SVC_DST (NSVC)
#define DEG_PN_SRC  (2*NSVC)
#define DEG_PN_DST  (2*NSVC + NPOD)
#define DEG_NP_SRC  (2*NSVC + NPOD + NNODE)
#define DEG_NP_DST  (2*NSVC + NPOD + 2*NNODE)
#define DEG_TOTAL   (2*NSVC + 2*NPOD + 2*NNODE)

#define OFF_SVC  0
#define OFF_NODE (NSVC)
#define OFF_POD  (NSVC + NNODE)
#define OFF_TOTAL (NSVC + NNODE + NPOD)

#define AGG_SVC_OFF  ((size_t)0)
#define AGG_NODE_OFF ((size_t)NSVC * FD)
#define AGG_POD_OFF  ((size_t)(NSVC + NNODE) * FD)
#define AGG_TOTAL    ((size_t)(NSVC + NNODE + NPOD) * FD)

// scan block mapping (1024-wide blocks)
#define NB_SVC  49
#define NB_NODE 20
#define NB_POD  98
#define NB_ALL  167

// gemm block mapping (128 rows/block)
#define GB_SVC  391
#define GB_NODE 157
#define GB_POD  782
#define GB_ALL  1330

__device__ float g_agg[AGG_TOTAL];
__device__ int   g_deg[DEG_TOTAL];
__device__ float g_nrm[DEG_TOTAL];
__device__ int   g_off[OFF_TOTAL];
__device__ int   g_fill[OFF_TOTAL];
__device__ int   g_part[3 * 128];
__device__ int   g_eidx_svc[ESVC_MAX];
__device__ int   g_eidx_pn[EPN_MAX];
__device__ int   g_eidx_np[ENP_MAX];

// fp16 weights (transposed [n][k]); only hi — A-side carries the residual
__device__ __half g_w1h[3][128 * 128];
__device__ __half g_w2h[3][64 * 128];

// ============================================================
// K1: zero counters + weight conversion (fused)
// ============================================================
__global__ void prep0(const float* __restrict__ W1_0, const float* __restrict__ W2_0,
                      const float* __restrict__ W1_1, const float* __restrict__ W2_1,
                      const float* __restrict__ W1_2, const float* __restrict__ W2_2) {
    int tid0 = blockIdx.x * blockDim.x + threadIdx.x;
    int stride = gridDim.x * blockDim.x;
    for (int i = tid0; i < DEG_TOTAL; i += stride) g_deg[i] = 0;
    for (int i = tid0; i < OFF_TOTAL; i += stride) g_fill[i] = 0;

    int idx = tid0;
    if (idx < 73728) {
        int t = idx / 24576;
        int r = idx % 24576;
        const float* W1 = (t == 0) ? W1_0 : (t == 1) ? W1_1 : W1_2;
        const float* W2 = (t == 0) ? W2_0 : (t == 1) ? W2_1 : W2_2;
        if (r < 16384) {
            int n = r >> 7, k = r & 127;
            g_w1h[t][n * 128 + k] = __float2half_rn(__ldg(W1 + k * 128 + n));
        } else {
            int q = r - 16384;
            int n = q >> 7, k = q & 127;
            g_w2h[t][n * 128 + k] = __float2half_rn(__ldg(W2 + k * 64 + n));
        }
    }
}

// ============================================================
// K2: degree counting, all three edge types in one grid
// ============================================================
__global__ void deg_all(const int* __restrict__ svc_src, const int* __restrict__ svc_dst,
                        const int* __restrict__ pn_src,  const int* __restrict__ pn_dst,
                        const int* __restrict__ np_src,  const int* __restrict__ np_dst,
                        int E_svc, int E_pn, int E_np) {
    int i = blockIdx.x * blockDim.x + threadIdx.x;
    if (i < E_svc) {
        atomicAdd(&g_deg[DEG_SVC_SRC + svc_src[i]], 1);
        atomicAdd(&g_deg[DEG_SVC_DST + svc_dst[i]], 1);
    } else if (i < E_svc + E_pn) {
        int e = i - E_svc;
        atomicAdd(&g_deg[DEG_PN_SRC + pn_src[e]], 1);
        atomicAdd(&g_deg[DEG_PN_DST + pn_dst[e]], 1);
    } else if (i < E_svc + E_pn + E_np) {
        int e = i - E_svc - E_pn;
        atomicAdd(&g_deg[DEG_NP_SRC + np_src[e]], 1);
        atomicAdd(&g_deg[DEG_NP_DST + np_dst[e]], 1);
    }
}

// ============================================================
// K3: per-type block scan (stage 1) + nrm computation
// ============================================================
__device__ __forceinline__ void scan_map(int b, int& t, int& lb,
                                         const int*& deg, int*& out, int& n) {
    if (b < NB_SVC)             { t = 0; lb = b;                    deg = g_deg + DEG_SVC_DST; out = g_off + OFF_SVC;  n = NSVC; }
    else if (b < NB_SVC+NB_NODE){ t = 1; lb = b - NB_SVC;           deg = g_deg + DEG_PN_DST;  out = g_off + OFF_NODE; n = NNODE; }
    else                        { t = 2; lb = b - NB_SVC - NB_NODE; deg = g_deg + DEG_NP_DST;  out = g_off + OFF_POD;  n = NPOD; }
}

__global__ void scan1_all() {
    {
        int tid0 = blockIdx.x * blockDim.x + threadIdx.x;
        int stride = gridDim.x * blockDim.x;
        for (int i = tid0; i < DEG_TOTAL; i += stride) {
            int d = g_deg[i];
            g_nrm[i] = rsqrtf((float)(d > 1 ? d : 1));
        }
    }
    __shared__ int s[1024];
    int t, lb, n;
    const int* deg;
    int* out;
    scan_map(blockIdx.x, t, lb, deg, out, n);
    int tt = threadIdx.x;
    int i = lb * 1024 + tt;
    int v = (i < n) ? deg[i] : 0;
    s[tt] = v;
    __syncthreads();
    #pragma unroll
    for (int d = 1; d < 1024; d <<= 1) {
        int tv = (tt >= d) ? s[tt - d] : 0;
        __syncthreads();
        s[tt] += tv;
        __syncthreads();
    }
    if (i < n) out[i] = s[tt] - v;
    if (tt == 1023) g_part[t * 128 + lb] = s[tt];
}

// ============================================================
// K4: merged scan2+scan3 — each block reduces the partials
// before its own local block index, then adds the carry.
// ============================================================
__global__ void scan23_all() {
    __shared__ int p[128];
    int t, lb, n;
    const int* deg;
    int* out;
    scan_map(blockIdx.x, t, lb, deg, out, n);
    int tt = threadIdx.x;
    if (tt < 128) p[tt] = (tt < lb) ? g_part[t * 128 + tt] : 0;
    __syncthreads();
    #pragma unroll
    for (int d = 64; d > 0; d >>= 1) {
        if (tt < d) p[tt] += p[tt + d];
        __syncthreads();
    }
    int carry = p[0];
    int i = lb * 1024 + tt;
    if (i < n) out[i] += carry;
}

// ============================================================
// K5: fill CSR edge lists, all types
// ============================================================
__global__ void fill_all(const int* __restrict__ svc_src, const int* __restrict__ svc_dst,
                         const int* __restrict__ pn_src,  const int* __restrict__ pn_dst,
                         const int* __restrict__ np_src,  const int* __restrict__ np_dst,
                         int E_svc, int E_pn, int E_np) {
    int i = blockIdx.x * blockDim.x + threadIdx.x;
    if (i < E_svc) {
        int d = svc_dst[i];
        int p = atomicAdd(&g_fill[OFF_SVC + d], 1);
        g_eidx_svc[g_off[OFF_SVC + d] + p] = svc_src[i];
    } else if (i < E_svc + E_pn) {
        int e = i - E_svc;
        int d = pn_dst[e];
        int p = atomicAdd(&g_fill[OFF_NODE + d], 1);
        g_eidx_pn[g_off[OFF_NODE + d] + p] = pn_src[e];
    } else if (i < E_svc + E_pn + E_np) {
        int e = i - E_svc - E_pn;
        int d = np_dst[e];
        int p = atomicAdd(&g_fill[OFF_POD + d], 1);
        g_eidx_np[g_off[OFF_POD + d] + p] = np_src[e];
    }
}

// ============================================================
// K6: warp-per-dst-row gather, all types in one grid
// ============================================================
__global__ void gather_all(const float* __restrict__ x_svc,
                           const float* __restrict__ x_pod,
                           const float* __restrict__ x_node) {
    int w = (blockIdx.x * blockDim.x + threadIdx.x) >> 5;
    int lane = threadIdx.x & 31;
    if (w >= OFF_TOTAL) return;

    const float* x;
    const int* eidx;
    const int* off;
    const int* cnt;
    const float* nsrc;
    const float* ndst;
    float* agg;
    int local;
    if (w < NSVC) {
        local = w;
        x = x_svc; eidx = g_eidx_svc; off = g_off + OFF_SVC;
        cnt = g_deg + DEG_SVC_DST; nsrc = g_nrm + DEG_SVC_SRC; ndst = g_nrm + DEG_SVC_DST;
        agg = g_agg + AGG_SVC_OFF;
    } else if (w < NSVC + NNODE) {
        local = w - NSVC;
        x = x_pod; eidx = g_eidx_pn; off = g_off + OFF_NODE;
        cnt = g_deg + DEG_PN_DST; nsrc = g_nrm + DEG_PN_SRC; ndst = g_nrm + DEG_PN_DST;
        agg = g_agg + AGG_NODE_OFF;
    } else {
        local = w - NSVC - NNODE;
        x = x_node; eidx = g_eidx_np; off = g_off + OFF_POD;
        cnt = g_deg + DEG_NP_DST; nsrc = g_nrm + DEG_NP_SRC; ndst = g_nrm + DEG_NP_DST;
        agg = g_agg + AGG_POD_OFF;
    }

    int beg = off[local];
    int end = beg + cnt[local];
    const float4* x4 = reinterpret_cast<const float4*>(x);

    float4 acc = make_float4(0.f, 0.f, 0.f, 0.f);
    int e = beg;
    for (; e + 4 <= end; e += 4) {
        int s0 = __ldg(eidx + e + 0);
        int s1 = __ldg(eidx + e + 1);
        int s2 = __ldg(eidx + e + 2);
        int s3 = __ldg(eidx + e + 3);
        float n0 = __ldg(nsrc + s0);
        float n1 = __ldg(nsrc + s1);
        float n2 = __ldg(nsrc + s2);
        float n3 = __ldg(nsrc + s3);
        float4 v0 = x4[(size_t)s0 * 32 + lane];
        float4 v1 = x4[(size_t)s1 * 32 + lane];
        float4 v2 = x4[(size_t)s2 * 32 + lane];
        float4 v3 = x4[(size_t)s3 * 32 + lane];
        acc.x += v0.x * n0; acc.y += v0.y * n0; acc.z += v0.z * n0; acc.w += v0.w * n0;
        acc.x += v1.x * n1; acc.y += v1.y * n1; acc.z += v1.z * n1; acc.w += v1.w * n1;
        acc.x += v2.x * n2; acc.y += v2.y * n2; acc.z += v2.z * n2; acc.w += v2.w * n2;
        acc.x += v3.x * n3; acc.y += v3.y * n3; acc.z += v3.z * n3; acc.w += v3.w * n3;
    }
    for (; e < end; e++) {
        int s0 = __ldg(eidx + e);
        float n0 = __ldg(nsrc + s0);
        float4 v0 = x4[(size_t)s0 * 32 + lane];
        acc.x += v0.x * n0; acc.y += v0.y * n0; acc.z += v0.z * n0; acc.w += v0.w * n0;
    }
    float nd = ndst[local];
    reinterpret_cast<float4*>(agg)[(size_t)local * 32 + lane] =
        make_float4(acc.x * nd, acc.y * nd, acc.z * nd, acc.w * nd);
}

// ============================================================
// K7: fused mma.sync fp16 2-product GEMM, all types in one grid
//   D1 = Ah@W1h + Al@W1h  (A = Ah+Al fp16 split; W residual dropped)
//   h  = leaky(D1 + b1) -> fp16 hi/lo
//   D2 = hh@W2h + hl@W2h ; out = D2 + b2
// ============================================================
#define SROWB 272
#define SM_A_HI 0
#define SM_A_LO 34816
#define SM_W1H  69632
#define SM_W2H  104448
#define SM_B1   121856
#define SM_B2   122368
#define SM_TOTAL 122624

__device__ __forceinline__ uint32_t pack_h2(__half a, __half b) {
    return (uint32_t)__half_as_ushort(a) | ((uint32_t)__half_as_ushort(b) << 16);
}
__device__ __forceinline__ void split_h(float v, __half& hi, __half& lo) {
    hi = __float2half_rn(v);
    lo = __float2half_rn(v - __half2float(hi));
}
__device__ __forceinline__ void mma_f16(float* c, uint32_t a0, uint32_t a1,
                                        uint32_t a2, uint32_t a3,
                                        uint32_t b0, uint32_t b1) {
    asm volatile(
        "mma.sync.aligned.m16n8k16.row.col.f32.f16.f16.f32 "
        "{%0,%1,%2,%3}, {%4,%5,%6,%7}, {%8,%9}, {%0,%1,%2,%3};"
        : "+f"(c[0]), "+f"(c[1]), "+f"(c[2]), "+f"(c[3])
        : "r"(a0), "r"(a1), "r"(a2), "r"(a3), "r"(b0), "r"(b1));
}
__device__ __forceinline__ uint32_t lds_u32(const char* base, int row, int col) {
    return *(const uint32_t*)(base + row * SROWB + col * 2);
}

__global__ void __launch_bounds__(256, 1)
gemm_all(const float* __restrict__ b_call, const float* __restrict__ b_lin_svc,
         const float* __restrict__ b_in,   const float* __restrict__ b_lin_node,
         const float* __restrict__ b_ni,   const float* __restrict__ b_lin_pod,
         float* __restrict__ out_base) {
    extern __shared__ char sm[];
    int tid = threadIdx.x;
    int wid = tid >> 5;
    int lane = tid & 31;
    int g = lane >> 2;
    int tig = lane & 3;

    int b = blockIdx.x;
    int t, lb, M;
    const float* agg;
    const float* b1;
    const float* b2;
    float* out;
    if (b < GB_SVC) {
        t = 0; lb = b; M = NSVC;
        agg = g_agg + AGG_SVC_OFF; b1 = b_call; b2 = b_lin_svc;
        out = out_base;
    } else if (b < GB_SVC + GB_NODE) {
        t = 1; lb = b - GB_SVC; M = NNODE;
        agg = g_agg + AGG_NODE_OFF; b1 = b_in; b2 = b_lin_node;
        out = out_base + (size_t)NSVC * OUTD;
    } else {
        t = 2; lb = b - GB_SVC - GB_NODE; M = NPOD;
        agg = g_agg + AGG_POD_OFF; b1 = b_ni; b2 = b_lin_pod;
        out = out_base + (size_t)(NSVC + NNODE) * OUTD;
    }

    // ---- stage weights ----
    {
        const uint4* s1 = (const uint4*)g_w1h[t];
        #pragma unroll
        for (int i = 0; i < 8; i++) {
            int idx = i * 256 + tid;
            int row = idx >> 4, gq = idx & 15;
            *(uint4*)(sm + SM_W1H + row * SROWB + gq * 16) = s1[idx];
        }
        const uint4* s2 = (const uint4*)g_w2h[t];
        #pragma unroll
        for (int i = 0; i < 4; i++) {
            int idx = i * 256 + tid;
            int row = idx >> 4, gq = idx & 15;
            *(uint4*)(sm + SM_W2H + row * SROWB + gq * 16) = s2[idx];
        }
    }
    if (tid < 128) ((float*)(sm + SM_B1))[tid] = b1[tid];
    else if (tid < 192) ((float*)(sm + SM_B2))[tid - 128] = b2[tid - 128];

    // ---- load + split A tile (fp16 hi/lo) ----
    {
        int row = tid >> 1;
        int half = (tid & 1) * 64;
        int grow = lb * 128 + row;
        const float4* av = (const float4*)agg + (size_t)grow * 32 + (half >> 2);
        #pragma unroll
        for (int j = 0; j < 16; j++) {
            float4 v = (grow < M) ? av[j] : make_float4(0.f, 0.f, 0.f, 0.f);
            __half h0, h1, h2, h3, l0, l1, l2, l3;
            split_h(v.x, h0, l0); split_h(v.y, h1, l1);
            split_h(v.z, h2, l2); split_h(v.w, h3, l3);
            int col = half + j * 4;
            *(uint2*)(sm + SM_A_HI + row * SROWB + col * 2) =
                make_uint2(pack_h2(h0, h1), pack_h2(h2, h3));
            *(uint2*)(sm + SM_A_LO + row * SROWB + col * 2) =
                make_uint2(pack_h2(l0, l1), pack_h2(l2, l3));
        }
    }
    __syncthreads();

    int mtb = (wid & 3) * 2;
    int nb1 = (wid >> 2) * 64;

    // ---- GEMM1 ----
    float acc[2][8][4];
    #pragma unroll
    for (int mt = 0; mt < 2; mt++)
        #pragma unroll
        for (int nt = 0; nt < 8; nt++)
            #pragma unroll
            for (int q = 0; q < 4; q++) acc[mt][nt][q] = 0.f;

    #pragma unroll
    for (int kc = 0; kc < 8; kc++) {
        int k0 = kc * 16 + tig * 2;
        uint32_t ah[2][4], al[2][4];
        #pragma unroll
        for (int mt = 0; mt < 2; mt++) {
            int r = (mtb + mt) * 16 + g;
            ah[mt][0] = lds_u32(sm + SM_A_HI, r,     k0);
            ah[mt][1] = lds_u32(sm + SM_A_HI, r + 8, k0);
            ah[mt][2] = lds_u32(sm + SM_A_HI, r,     k0 + 8);
            ah[mt][3] = lds_u32(sm + SM_A_HI, r + 8, k0 + 8);
            al[mt][0] = lds_u32(sm + SM_A_LO, r,     k0);
            al[mt][1] = lds_u32(sm + SM_A_LO, r + 8, k0);
            al[mt][2] = lds_u32(sm + SM_A_LO, r,     k0 + 8);
            al[mt][3] = lds_u32(sm + SM_A_LO, r + 8, k0 + 8);
        }
        #pragma unroll
        for (int nt = 0; nt < 8; nt++) {
            int n = nb1 + nt * 8 + g;
            uint32_t bh0 = lds_u32(sm + SM_W1H, n, k0);
            uint32_t bh1 = lds_u32(sm + SM_W1H, n, k0 + 8);
            #pragma unroll
            for (int mt = 0; mt < 2; mt++) {
                mma_f16(acc[mt][nt], ah[mt][0], ah[mt][1], ah[mt][2], ah[mt][3], bh0, bh1);
                mma_f16(acc[mt][nt], al[mt][0], al[mt][1], al[mt][2], al[mt][3], bh0, bh1);
            }
        }
    }
    __syncthreads();

    // ---- epilogue1: bias + leaky + fp16 re-split ----
    {
        const float* b1s = (const float*)(sm + SM_B1);
        #pragma unroll
        for (int mt = 0; mt < 2; mt++) {
            #pragma unroll
            for (int nt = 0; nt < 8; nt++) {
                int row = (mtb + mt) * 16 + g;
                int col = nb1 + nt * 8 + tig * 2;
                float bb0 = b1s[col], bb1 = b1s[col + 1];
                float v0 = acc[mt][nt][0] + bb0;
                float v1 = acc[mt][nt][1] + bb1;
                float v2 = acc[mt][nt][2] + bb0;
                float v3 = acc[mt][nt][3] + bb1;
                v0 = v0 > 0.f ? v0 : 0.01f * v0;
                v1 = v1 > 0.f ? v1 : 0.01f * v1;
                v2 = v2 > 0.f ? v2 : 0.01f * v2;
                v3 = v3 > 0.f ? v3 : 0.01f * v3;
                __half h0, h1, h2, h3, l0, l1, l2, l3;
                split_h(v0, h0, l0); split_h(v1, h1, l1);
                split_h(v2, h2, l2); split_h(v3, h3, l3);
                *(uint32_t*)(sm + SM_A_HI + row * SROWB + col * 2) = pack_h2(h0, h1);
                *(uint32_t*)(sm + SM_A_LO + row * SROWB + col * 2) = pack_h2(l0, l1);
                *(uint32_t*)(sm + SM_A_HI + (row + 8) * SROWB + col * 2) = pack_h2(h2, h3);
                *(uint32_t*)(sm + SM_A_LO + (row + 8) * SROWB + col * 2) = pack_h2(l2, l3);
            }
        }
    }
    __syncthreads();

    // ---- GEMM2 ----
    int nb2 = (wid >> 2) * 32;
    float acc2[2][4][4];
    #pragma unroll
    for (int mt = 0; mt < 2; mt++)
        #pragma unroll
        for (int nt = 0; nt < 4; nt++)
            #pragma unroll
            for (int q = 0; q < 4; q++) acc2[mt][nt][q] = 0.f;

    #pragma unroll
    for (int kc = 0; kc < 8; kc++) {
        int k0 = kc * 16 + tig * 2;
        uint32_t ah[2][4], al[2][4];
        #pragma unroll
        for (int mt = 0; mt < 2; mt++) {
            int r = (mtb + mt) * 16 + g;
            ah[mt][0] = lds_u32(sm + SM_A_HI, r,     k0);
            ah[mt][1] = lds_u32(sm + SM_A_HI, r + 8, k0);
            ah[mt][2] = lds_u32(sm + SM_A_HI, r,     k0 + 8);
            ah[mt][3] = lds_u32(sm + SM_A_HI, r + 8, k0 + 8);
            al[mt][0] = lds_u32(sm + SM_A_LO, r,     k0);
            al[mt][1] = lds_u32(sm + SM_A_LO, r + 8, k0);
            al[mt][2] = lds_u32(sm + SM_A_LO, r,     k0 + 8);
            al[mt][3] = lds_u32(sm + SM_A_LO, r + 8, k0 + 8);
        }
        #pragma unroll
        for (int nt = 0; nt < 4; nt++) {
            int n = nb2 + nt * 8 + g;
            uint32_t bh0 = lds_u32(sm + SM_W2H, n, k0);
            uint32_t bh1 = lds_u32(sm + SM_W2H, n, k0 + 8);
            #pragma unroll
            for (int mt = 0; mt < 2; mt++) {
                mma_f16(acc2[mt][nt], ah[mt][0], ah[mt][1], ah[mt][2], ah[mt][3], bh0, bh1);
                mma_f16(acc2[mt][nt], al[mt][0], al[mt][1], al[mt][2], al[mt][3], bh0, bh1);
            }
        }
    }

    // ---- epilogue2 ----
    {
        const float* b2s = (const float*)(sm + SM_B2);
        #pragma unroll
        for (int mt = 0; mt < 2; mt++) {
            #pragma unroll
            for (int nt = 0; nt < 4; nt++) {
                int row = lb * 128 + (mtb + mt) * 16 + g;
                int col = nb2 + nt * 8 + tig * 2;
                float bb0 = b2s[col], bb1 = b2s[col + 1];
                if (row < M)
                    *(float2*)(out + (size_t)row * 64 + col) =
                        make_float2(acc2[mt][nt][0] + bb0, acc2[mt][nt][1] + bb1);
                if (row + 8 < M)
                    *(float2*)(out + (size_t)(row + 8) * 64 + col) =
                        make_float2(acc2[mt][nt][2] + bb0, acc2[mt][nt][3] + bb1);
            }
        }
    }
}

// ============================================================
// launch — 7 kernels total
// ============================================================
extern "C" void kernel_launch(void* const* d_in, const int* in_sizes, int n_in,
                              void* d_out, int out_size) {
    const float* x_svc  = (const float*)d_in[0];
    const float* x_pod  = (const float*)d_in[1];
    const float* x_node = (const float*)d_in[2];
    const int* svc_src = (const int*)d_in[3];
    const int* svc_dst = (const int*)d_in[4];
    const int* pn_src  = (const int*)d_in[5];
    const int* pn_dst  = (const int*)d_in[6];
    const int* np_src  = (const int*)d_in[7];
    const int* np_dst  = (const int*)d_in[8];
    const float* W_call = (const float*)d_in[9];
    const float* b_call = (const float*)d_in[10];
    const float* W_in   = (const float*)d_in[11];
    const float* b_in   = (const float*)d_in[12];
    const float* W_ni   = (const float*)d_in[13];
    const float* b_ni   = (const float*)d_in[14];
    const float* W_lin_svc  = (const float*)d_in[15];
    const float* b_lin_svc  = (const float*)d_in[16];
    const float* W_lin_node = (const float*)d_in[17];
    const float* b_lin_node = (const float*)d_in[18];
    const float* W_lin_pod  = (const float*)d_in[19];
    const float* b_lin_pod  = (const float*)d_in[20];
    float* out = (float*)d_out;

    int E_svc = in_sizes[3];
    int E_pn  = in_sizes[5];
    int E_np  = in_sizes[7];
    int E_tot = E_svc + E_pn + E_np;

    cudaFuncSetAttribute(gemm_all, cudaFuncAttributeMaxDynamicSharedMemorySize, SM_TOTAL);

    prep0<<<512, 256>>>(W_call, W_lin_svc, W_in, W_lin_node, W_ni, W_lin_pod);

    deg_all<<<(E_tot + 255) / 256, 256>>>(svc_src, svc_dst, pn_src, pn_dst,
                                          np_src, np_dst, E_svc, E_pn, E_np);

    scan1_all<<<NB_ALL, 1024>>>();
    scan23_all<<<NB_ALL, 1024>>>();

    fill_all<<<(E_tot + 255) / 256, 256>>>(svc_src, svc_dst, pn_src, pn_dst,
                                           np_src, np_dst, E_svc, E_pn, E_np);

    gather_all<<<(OFF_TOTAL + 7) / 8, 256>>>(x_svc, x_pod, x_node);

    gemm_all<<<GB_ALL, 256, SM_TOTAL>>>(b_call, b_lin_svc, b_in, b_lin_node,
                                        b_ni, b_lin_pod, out);
}